// round 7
// baseline (speedup 1.0000x reference)
#include <cuda_runtime.h>
#include <cuda_bf16.h>
#include <cstdint>

#define T_TOK 8192
#define H_DIM 2048
#define I_DIM 8192
#define NW    16777216

// ---------------- device scratch ----------------
__device__ float       g_part[3 * 1024];
__device__ float       g_wnorm[3];
__device__ signed char g_wqg[NW];
__device__ signed char g_wqu[NW];
__device__ signed char g_wqd[NW];
__device__ signed char g_xq[T_TOK * H_DIM];
__device__ float       g_xs[T_TOK];
__device__ float       g_inter[67108864];   // fp32 silu(gate)*up [T,I]
__device__ signed char g_aq2[67108864];     // int8 quantized fwht(inter)
__device__ float       g_as2[T_TOK];

// ---------------- helpers ----------------
__device__ __forceinline__ uint32_t smem_u32(const void* p) {
    uint32_t a;
    asm("{ .reg .u64 t; cvta.to.shared.u64 t, %1; cvt.u32.u64 %0, t; }" : "=r"(a) : "l"(p));
    return a;
}
#define CP_ASYNC16(dst, src) \
    asm volatile("cp.async.cg.shared.global [%0], [%1], 16;" :: "r"(dst), "l"(src) : "memory")
#define CP_COMMIT() asm volatile("cp.async.commit_group;" ::: "memory")
#define CP_WAIT(n)  asm volatile("cp.async.wait_group %0;" :: "n"(n) : "memory")

#define MMA_S8(C, A, B) \
    asm volatile("mma.sync.aligned.m16n8k32.row.col.s32.s8.s8.s32 " \
        "{%0,%1,%2,%3}, {%4,%5,%6,%7}, {%8,%9}, {%0,%1,%2,%3};" \
        : "+r"((C)[0]), "+r"((C)[1]), "+r"((C)[2]), "+r"((C)[3]) \
        : "r"((A)[0]), "r"((A)[1]), "r"((A)[2]), "r"((A)[3]), "r"((B)[0]), "r"((B)[1]))

#define LDSM_X4(R0, R1, R2, R3, addr) \
    asm volatile("ldmatrix.sync.aligned.m8n8.x4.shared.b16 {%0,%1,%2,%3}, [%4];" \
        : "=r"(R0), "=r"(R1), "=r"(R2), "=r"(R3) : "r"(addr))

__device__ __forceinline__ int pack_q4(float4 v, float s, float lo, float hi) {
    int q0 = (int)fminf(fmaxf(rintf(v.x * s), lo), hi);
    int q1 = (int)fminf(fmaxf(rintf(v.y * s), lo), hi);
    int q2 = (int)fminf(fmaxf(rintf(v.z * s), lo), hi);
    int q3 = (int)fminf(fmaxf(rintf(v.w * s), lo), hi);
    return (q0 & 0xff) | ((q1 & 0xff) << 8) | ((q2 & 0xff) << 16) | ((q3 & 0xff) << 24);
}

// ---------------- 1) |w| partial reduction ----------------
__global__ void k_wabs(const float* __restrict__ w0, const float* __restrict__ w1,
                       const float* __restrict__ w2) {
    __shared__ float red[256];
    const float* W = (blockIdx.y == 0) ? w0 : ((blockIdx.y == 1) ? w1 : w2);
    float s = 0.f;
    for (int idx = blockIdx.x * 256 + threadIdx.x; idx < NW / 4; idx += 1024 * 256) {
        float4 v = reinterpret_cast<const float4*>(W)[idx];
        s += fabsf(v.x) + fabsf(v.y) + fabsf(v.z) + fabsf(v.w);
    }
    red[threadIdx.x] = s;
    __syncthreads();
    for (int o = 128; o > 0; o >>= 1) {
        if (threadIdx.x < o) red[threadIdx.x] += red[threadIdx.x + o];
        __syncthreads();
    }
    if (threadIdx.x == 0) g_part[blockIdx.y * 1024 + blockIdx.x] = red[0];
}

// ---------------- 2) finalize mean|w| ----------------
__global__ void k_wfin() {
    __shared__ float red[1024];
    int m = blockIdx.x;
    red[threadIdx.x] = g_part[m * 1024 + threadIdx.x];
    __syncthreads();
    for (int o = 512; o > 0; o >>= 1) {
        if (threadIdx.x < o) red[threadIdx.x] += red[threadIdx.x + o];
        __syncthreads();
    }
    if (threadIdx.x == 0) g_wnorm[m] = fmaxf(red[0] / (float)NW, 1e-5f);
}

// ---------------- 3) ternarize weights ----------------
__global__ void k_wquant(const float* __restrict__ w0, const float* __restrict__ w1,
                         const float* __restrict__ w2) {
    int m = blockIdx.y;
    const float* W = (m == 0) ? w0 : ((m == 1) ? w1 : w2);
    signed char* Q = (m == 0) ? g_wqg : ((m == 1) ? g_wqu : g_wqd);
    float ws = 1.0f / g_wnorm[m];
    int i4 = blockIdx.x * 256 + threadIdx.x;
    const float4* Wv = reinterpret_cast<const float4*>(W);
    int4 o;
    o.x = pack_q4(Wv[i4 * 4 + 0], ws, -1.f, 1.f);
    o.y = pack_q4(Wv[i4 * 4 + 1], ws, -1.f, 1.f);
    o.z = pack_q4(Wv[i4 * 4 + 2], ws, -1.f, 1.f);
    o.w = pack_q4(Wv[i4 * 4 + 3], ws, -1.f, 1.f);
    reinterpret_cast<int4*>(Q)[i4] = o;
}

// ---------------- 4) per-token act_quant of x ----------------
__global__ void k_actq1(const float* __restrict__ x) {
    __shared__ float red[256];
    int t = blockIdx.x;
    const float4* px = reinterpret_cast<const float4*>(x + (size_t)t * H_DIM);
    float4 v0 = px[threadIdx.x * 2], v1 = px[threadIdx.x * 2 + 1];
    float m = fmaxf(fmaxf(fmaxf(fabsf(v0.x), fabsf(v0.y)), fmaxf(fabsf(v0.z), fabsf(v0.w))),
                    fmaxf(fmaxf(fabsf(v1.x), fabsf(v1.y)), fmaxf(fabsf(v1.z), fabsf(v1.w))));
    red[threadIdx.x] = m;
    __syncthreads();
    for (int o = 128; o > 0; o >>= 1) {
        if (threadIdx.x < o) red[threadIdx.x] = fmaxf(red[threadIdx.x], red[threadIdx.x + o]);
        __syncthreads();
    }
    float scale = 128.f / fmaxf(red[0], 1e-5f);
    int p0 = pack_q4(v0, scale, -128.f, 127.f);
    int p1 = pack_q4(v1, scale, -128.f, 127.f);
    reinterpret_cast<int2*>(g_xq + (size_t)t * H_DIM)[threadIdx.x] = make_int2(p0, p1);
    if (threadIdx.x == 0) g_xs[t] = scale;
}

// ---------------- GEMM common geometry ----------------
// BM=256, 128 B-rows, BK=64, 16 warps 4(M)x4(N), warp tile 64x32, 4-stage cp.async,
// ldmatrix fragment loads. 512 threads.
#define SSTRIDE 80
#define A_SZ    (256 * SSTRIDE)   // 20480 B per stage
#define B_SZ    (128 * SSTRIDE)   // 10240 B per stage
#define NSTG    4
#define DSMEM   (NSTG * (A_SZ + B_SZ))  // 122880 B

// ---------------- 5) GEMM1: IMMA, gate+up interleaved, SiLU epilogue ----------------
__global__ __launch_bounds__(512, 1) void k_gemm1() {
    extern __shared__ signed char dyn[];
    const int tid = threadIdx.x, wid = tid >> 5, lane = tid & 31;
    const int gid = lane >> 2, tig = lane & 3;
    const int wm = wid >> 2, wn = wid & 3;
    const int m0 = blockIdx.y * 256, n0 = blockIdx.x * 64;
    const signed char* A = g_xq + (size_t)m0 * H_DIM;

    const int rowA = (lane & 7) + ((lane >> 3) & 1) * 8;
    const int bytA = ((lane >> 4) & 1) * 16;
    const int rowB = (lane & 7) + ((lane >> 4) & 1) * 8;
    const int bytB = ((lane >> 3) & 1) * 16;
    const uint32_t dynb = smem_u32(dyn);

    int c[4][4][4];
#pragma unroll
    for (int i = 0; i < 4; i++)
#pragma unroll
        for (int j = 0; j < 4; j++)
#pragma unroll
            for (int q = 0; q < 4; q++) c[i][j][q] = 0;

    auto load_stage = [&](int st, int kb) {
        int koff = kb * 64;
        signed char* dA = dyn + st * A_SZ;
        signed char* dB = dyn + NSTG * A_SZ + st * B_SZ;
#pragma unroll
        for (int l = 0; l < 2; l++) {          // A: 256 rows x 4 chunks = 1024
            int ch = tid + l * 512;
            int r = ch >> 2, c16 = ch & 3;
            CP_ASYNC16(smem_u32(&dA[r * SSTRIDE + c16 * 16]),
                       A + (size_t)r * H_DIM + koff + c16 * 16);
        }
        {                                       // B: 128 rows x 4 chunks = 512
            int r = tid >> 2, c16 = tid & 3;
            int n = n0 + (r >> 1);
            const signed char* W = (r & 1) ? g_wqu : g_wqg;
            CP_ASYNC16(smem_u32(&dB[r * SSTRIDE + c16 * 16]),
                       W + (size_t)n * H_DIM + koff + c16 * 16);
        }
    };

    load_stage(0, 0); CP_COMMIT();
    load_stage(1, 1); CP_COMMIT();
    load_stage(2, 2); CP_COMMIT();

    const int NKB = 32;
    for (int kb = 0; kb < NKB; kb++) {
        if (kb < NKB - 2)      { CP_WAIT(2); }
        else if (kb == NKB - 2){ CP_WAIT(1); }
        else                   { CP_WAIT(0); }
        __syncthreads();
        if (kb + 3 < NKB) { load_stage((kb + 3) & 3, kb + 3); CP_COMMIT(); }
        int st = kb & 3;
        uint32_t As = dynb + st * A_SZ;
        uint32_t Bs = dynb + NSTG * A_SZ + st * B_SZ;
#pragma unroll
        for (int ks = 0; ks < 2; ks++) {
            int a[4][4], b[4][2];
#pragma unroll
            for (int mi = 0; mi < 4; mi++) {
                uint32_t ad = As + (uint32_t)(wm * 64 + mi * 16 + rowA) * SSTRIDE + ks * 32 + bytA;
                LDSM_X4(a[mi][0], a[mi][1], a[mi][2], a[mi][3], ad);
            }
#pragma unroll
            for (int np = 0; np < 2; np++) {
                uint32_t bd = Bs + (uint32_t)(wn * 32 + np * 16 + rowB) * SSTRIDE + ks * 32 + bytB;
                LDSM_X4(b[2 * np][0], b[2 * np][1], b[2 * np + 1][0], b[2 * np + 1][1], bd);
            }
#pragma unroll
            for (int mi = 0; mi < 4; mi++)
#pragma unroll
                for (int ni = 0; ni < 4; ni++) MMA_S8(c[mi][ni], a[mi], b[ni]);
        }
    }

    float fg = g_wnorm[0], fu = g_wnorm[1];
#pragma unroll
    for (int mi = 0; mi < 4; mi++) {
        int t1 = m0 + wm * 64 + mi * 16 + gid, t2 = t1 + 8;
        float i1 = 1.0f / g_xs[t1], i2 = 1.0f / g_xs[t2];
#pragma unroll
        for (int ni = 0; ni < 4; ni++) {
            int n = n0 + wn * 16 + ni * 4 + tig;
            float gv1 = (float)c[mi][ni][0] * fg * i1;
            float uv1 = (float)c[mi][ni][1] * fu * i1;
            g_inter[(size_t)t1 * I_DIM + n] = gv1 / (1.0f + __expf(-gv1)) * uv1;
            float gv2 = (float)c[mi][ni][2] * fg * i2;
            float uv2 = (float)c[mi][ni][3] * fu * i2;
            g_inter[(size_t)t2 * I_DIM + n] = gv2 / (1.0f + __expf(-gv2)) * uv2;
        }
    }
}

// ---------------- 6) FWHT-8192 + act_quant #2 (register-chunked) ----------------
__global__ __launch_bounds__(512) void k_fwht() {
    __shared__ float s[8192];
    __shared__ float red[512];
    const int tid = threadIdx.x;
    const int t = blockIdx.x;
    float v[16];
    float4* vv = reinterpret_cast<float4*>(v);

    const float4* src = reinterpret_cast<const float4*>(g_inter + (size_t)t * I_DIM);
#pragma unroll
    for (int i = 0; i < 4; i++) vv[i] = src[tid * 4 + i];
#pragma unroll
    for (int h = 1; h < 16; h <<= 1)
#pragma unroll
        for (int i = 0; i < 16; i++)
            if ((i & h) == 0) {
                float a = v[i], b = v[i + h];
                v[i] = a + b; v[i + h] = a - b;
            }
#pragma unroll
    for (int i = 0; i < 4; i++) reinterpret_cast<float4*>(s)[tid * 4 + i] = vv[i];
    __syncthreads();

    int b2 = (tid & 15) + ((tid >> 4) << 8);
#pragma unroll
    for (int j = 0; j < 16; j++) v[j] = s[b2 + 16 * j];
#pragma unroll
    for (int h = 1; h < 16; h <<= 1)
#pragma unroll
        for (int j = 0; j < 16; j++)
            if ((j & h) == 0) {
                float a = v[j], b = v[j + h];
                v[j] = a + b; v[j + h] = a - b;
            }
#pragma unroll
    for (int j = 0; j < 16; j++) s[b2 + 16 * j] = v[j];
    __syncthreads();

    int b3 = (tid & 255) + ((tid >> 8) << 12);
#pragma unroll
    for (int j = 0; j < 16; j++) v[j] = s[b3 + 256 * j];
#pragma unroll
    for (int h = 1; h < 16; h <<= 1)
#pragma unroll
        for (int j = 0; j < 16; j++)
            if ((j & h) == 0) {
                float a = v[j], b = v[j + h];
                v[j] = a + b; v[j + h] = a - b;
            }
#pragma unroll
    for (int j = 0; j < 16; j++) s[b3 + 256 * j] = v[j];
    __syncthreads();

    const float rn = 1.1048543456039805e-02f;  // 1/sqrt(8192)
    float lo[8], hi[8];
    float m = 0.f;
#pragma unroll
    for (int q = 0; q < 8; q++) {
        float a = s[tid * 8 + q], b = s[tid * 8 + q + 4096];
        float na = (a + b) * rn, nb = (a - b) * rn;
        lo[q] = na; hi[q] = nb;
        m = fmaxf(m, fmaxf(fabsf(na), fabsf(nb)));
    }
    red[tid] = m;
    __syncthreads();
    for (int o = 256; o > 0; o >>= 1) {
        if (tid < o) red[tid] = fmaxf(red[tid], red[tid + o]);
        __syncthreads();
    }
    float scale = 128.f / fmaxf(red[0], 1e-5f);
    float4* lv = reinterpret_cast<float4*>(lo);
    float4* hv = reinterpret_cast<float4*>(hi);
    int2 plo = make_int2(pack_q4(lv[0], scale, -128.f, 127.f),
                         pack_q4(lv[1], scale, -128.f, 127.f));
    int2 phi = make_int2(pack_q4(hv[0], scale, -128.f, 127.f),
                         pack_q4(hv[1], scale, -128.f, 127.f));
    int2* orow = reinterpret_cast<int2*>(g_aq2 + (size_t)t * I_DIM);
    orow[tid] = plo;
    orow[tid + 512] = phi;
    if (tid == 0) g_as2[t] = scale;
}

// ---------------- 7) GEMM2: IMMA down projection ----------------
__global__ __launch_bounds__(512, 1) void k_gemm2(float* __restrict__ out) {
    extern __shared__ signed char dyn[];
    const int tid = threadIdx.x, wid = tid >> 5, lane = tid & 31;
    const int gid = lane >> 2, tig = lane & 3;
    const int wm = wid >> 2, wn = wid & 3;
    const int m0 = blockIdx.y * 256, n0 = blockIdx.x * 128;
    const signed char* A = g_aq2 + (size_t)m0 * I_DIM;
    const signed char* B = g_wqd + (size_t)n0 * I_DIM;

    const int rowA = (lane & 7) + ((lane >> 3) & 1) * 8;
    const int bytA = ((lane >> 4) & 1) * 16;
    const int rowB = (lane & 7) + ((lane >> 4) & 1) * 8;
    const int bytB = ((lane >> 3) & 1) * 16;
    const uint32_t dynb = smem_u32(dyn);

    int c[4][4][4];
#pragma unroll
    for (int i = 0; i < 4; i++)
#pragma unroll
        for (int j = 0; j < 4; j++)
#pragma unroll
            for (int q = 0; q < 4; q++) c[i][j][q] = 0;

    auto load_stage = [&](int st, int kb) {
        int koff = kb * 64;
        signed char* dA = dyn + st * A_SZ;
        signed char* dB = dyn + NSTG * A_SZ + st * B_SZ;
#pragma unroll
        for (int l = 0; l < 2; l++) {
            int ch = tid + l * 512;
            int r = ch >> 2, c16 = ch & 3;
            CP_ASYNC16(smem_u32(&dA[r * SSTRIDE + c16 * 16]),
                       A + (size_t)r * I_DIM + koff + c16 * 16);
        }
        {
            int r = tid >> 2, c16 = tid & 3;
            CP_ASYNC16(smem_u32(&dB[r * SSTRIDE + c16 * 16]),
                       B + (size_t)r * I_DIM + koff + c16 * 16);
        }
    };

    load_stage(0, 0); CP_COMMIT();
    load_stage(1, 1); CP_COMMIT();
    load_stage(2, 2); CP_COMMIT();

    const int NKB = 128;
    for (int kb = 0; kb < NKB; kb++) {
        if (kb < NKB - 2)      { CP_WAIT(2); }
        else if (kb == NKB - 2){ CP_WAIT(1); }
        else                   { CP_WAIT(0); }
        __syncthreads();
        if (kb + 3 < NKB) { load_stage((kb + 3) & 3, kb + 3); CP_COMMIT(); }
        int st = kb & 3;
        uint32_t As = dynb + st * A_SZ;
        uint32_t Bs = dynb + NSTG * A_SZ + st * B_SZ;
#pragma unroll
        for (int ks = 0; ks < 2; ks++) {
            int a[4][4], b[4][2];
#pragma unroll
            for (int mi = 0; mi < 4; mi++) {
                uint32_t ad = As + (uint32_t)(wm * 64 + mi * 16 + rowA) * SSTRIDE + ks * 32 + bytA;
                LDSM_X4(a[mi][0], a[mi][1], a[mi][2], a[mi][3], ad);
            }
#pragma unroll
            for (int np = 0; np < 2; np++) {
                uint32_t bd = Bs + (uint32_t)(wn * 32 + np * 16 + rowB) * SSTRIDE + ks * 32 + bytB;
                LDSM_X4(b[2 * np][0], b[2 * np][1], b[2 * np + 1][0], b[2 * np + 1][1], bd);
            }
#pragma unroll
            for (int mi = 0; mi < 4; mi++)
#pragma unroll
                for (int ni = 0; ni < 4; ni++) MMA_S8(c[mi][ni], a[mi], b[ni]);
        }
    }

    float fw = g_wnorm[2];
#pragma unroll
    for (int mi = 0; mi < 4; mi++) {
        int t1 = m0 + wm * 64 + mi * 16 + gid, t2 = t1 + 8;
        float f1 = fw / g_as2[t1], f2 = fw / g_as2[t2];
#pragma unroll
        for (int ni = 0; ni < 4; ni++) {
            int col = n0 + wn * 32 + ni * 8 + tig * 2;
            float2 o1 = make_float2((float)c[mi][ni][0] * f1, (float)c[mi][ni][1] * f1);
            float2 o2 = make_float2((float)c[mi][ni][2] * f2, (float)c[mi][ni][3] * f2);
            *reinterpret_cast<float2*>(&out[(size_t)t1 * H_DIM + col]) = o1;
            *reinterpret_cast<float2*>(&out[(size_t)t2 * H_DIM + col]) = o2;
        }
    }
}

// ---------------- launch ----------------
extern "C" void kernel_launch(void* const* d_in, const int* in_sizes, int n_in,
                              void* d_out, int out_size) {
    const float* x  = (const float*)d_in[0];
    const float* wg = (const float*)d_in[1];
    const float* wu = (const float*)d_in[2];
    const float* wd = (const float*)d_in[3];
    float* out = (float*)d_out;

    static int configured = 0;
    if (!configured) {
        cudaFuncSetAttribute(k_gemm1, cudaFuncAttributeMaxDynamicSharedMemorySize, DSMEM);
        cudaFuncSetAttribute(k_gemm2, cudaFuncAttributeMaxDynamicSharedMemorySize, DSMEM);
        configured = 1;
    }

    k_wabs<<<dim3(1024, 3), 256>>>(wg, wu, wd);
    k_wfin<<<3, 1024>>>();
    k_wquant<<<dim3(4096, 3), 256>>>(wg, wu, wd);
    k_actq1<<<T_TOK, 256>>>(x);
    k_gemm1<<<dim3(I_DIM / 64, T_TOK / 256), 512, DSMEM>>>();
    k_fwht<<<T_TOK, 512>>>();
    k_gemm2<<<dim3(H_DIM / 128, T_TOK / 256), 512, DSMEM>>>(out);
}

// round 8
// speedup vs baseline: 1.1208x; 1.1208x over previous
#include <cuda_runtime.h>
#include <cuda_bf16.h>
#include <cstdint>

#define T_TOK 8192
#define H_DIM 2048
#define I_DIM 8192
#define NW    16777216

// ---------------- device scratch ----------------
__device__ float       g_part[3 * 1024];
__device__ float       g_wnorm[3];
__device__ signed char g_wqg[NW];
__device__ signed char g_wqu[NW];
__device__ signed char g_wqd[NW];
__device__ signed char g_xq[T_TOK * H_DIM];
__device__ float       g_xs[T_TOK];
__device__ float       g_inter[67108864];   // fp32 silu(gate)*up [T,I]
__device__ signed char g_aq2[67108864];     // int8 quantized fwht(inter)
__device__ float       g_as2[T_TOK];

// ---------------- helpers ----------------
__device__ __forceinline__ uint32_t smem_u32(const void* p) {
    uint32_t a;
    asm("{ .reg .u64 t; cvta.to.shared.u64 t, %1; cvt.u32.u64 %0, t; }" : "=r"(a) : "l"(p));
    return a;
}
#define CP_ASYNC16(dst, src) \
    asm volatile("cp.async.cg.shared.global [%0], [%1], 16;" :: "r"(dst), "l"(src) : "memory")
#define CP_COMMIT() asm volatile("cp.async.commit_group;" ::: "memory")
#define CP_WAIT(n)  asm volatile("cp.async.wait_group %0;" :: "n"(n) : "memory")

#define MMA_S8(C, A, B) \
    asm volatile("mma.sync.aligned.m16n8k32.row.col.s32.s8.s8.s32 " \
        "{%0,%1,%2,%3}, {%4,%5,%6,%7}, {%8,%9}, {%0,%1,%2,%3};" \
        : "+r"((C)[0]), "+r"((C)[1]), "+r"((C)[2]), "+r"((C)[3]) \
        : "r"((A)[0]), "r"((A)[1]), "r"((A)[2]), "r"((A)[3]), "r"((B)[0]), "r"((B)[1]))

#define LDSM_X4(R0, R1, R2, R3, addr) \
    asm volatile("ldmatrix.sync.aligned.m8n8.x4.shared.b16 {%0,%1,%2,%3}, [%4];" \
        : "=r"(R0), "=r"(R1), "=r"(R2), "=r"(R3) : "r"(addr))

__device__ __forceinline__ int pack_q4(float4 v, float s, float lo, float hi) {
    int q0 = (int)fminf(fmaxf(rintf(v.x * s), lo), hi);
    int q1 = (int)fminf(fmaxf(rintf(v.y * s), lo), hi);
    int q2 = (int)fminf(fmaxf(rintf(v.z * s), lo), hi);
    int q3 = (int)fminf(fmaxf(rintf(v.w * s), lo), hi);
    return (q0 & 0xff) | ((q1 & 0xff) << 8) | ((q2 & 0xff) << 16) | ((q3 & 0xff) << 24);
}

// ---------------- 1) |w| partial reduction ----------------
__global__ void k_wabs(const float* __restrict__ w0, const float* __restrict__ w1,
                       const float* __restrict__ w2) {
    __shared__ float red[256];
    const float* W = (blockIdx.y == 0) ? w0 : ((blockIdx.y == 1) ? w1 : w2);
    float s = 0.f;
    for (int idx = blockIdx.x * 256 + threadIdx.x; idx < NW / 4; idx += 1024 * 256) {
        float4 v = reinterpret_cast<const float4*>(W)[idx];
        s += fabsf(v.x) + fabsf(v.y) + fabsf(v.z) + fabsf(v.w);
    }
    red[threadIdx.x] = s;
    __syncthreads();
    for (int o = 128; o > 0; o >>= 1) {
        if (threadIdx.x < o) red[threadIdx.x] += red[threadIdx.x + o];
        __syncthreads();
    }
    if (threadIdx.x == 0) g_part[blockIdx.y * 1024 + blockIdx.x] = red[0];
}

// ---------------- 2) finalize mean|w| ----------------
__global__ void k_wfin() {
    __shared__ float red[1024];
    int m = blockIdx.x;
    red[threadIdx.x] = g_part[m * 1024 + threadIdx.x];
    __syncthreads();
    for (int o = 512; o > 0; o >>= 1) {
        if (threadIdx.x < o) red[threadIdx.x] += red[threadIdx.x + o];
        __syncthreads();
    }
    if (threadIdx.x == 0) g_wnorm[m] = fmaxf(red[0] / (float)NW, 1e-5f);
}

// ---------------- 3) ternarize weights ----------------
__global__ void k_wquant(const float* __restrict__ w0, const float* __restrict__ w1,
                         const float* __restrict__ w2) {
    int m = blockIdx.y;
    const float* W = (m == 0) ? w0 : ((m == 1) ? w1 : w2);
    signed char* Q = (m == 0) ? g_wqg : ((m == 1) ? g_wqu : g_wqd);
    float ws = 1.0f / g_wnorm[m];
    int i4 = blockIdx.x * 256 + threadIdx.x;
    const float4* Wv = reinterpret_cast<const float4*>(W);
    int4 o;
    o.x = pack_q4(Wv[i4 * 4 + 0], ws, -1.f, 1.f);
    o.y = pack_q4(Wv[i4 * 4 + 1], ws, -1.f, 1.f);
    o.z = pack_q4(Wv[i4 * 4 + 2], ws, -1.f, 1.f);
    o.w = pack_q4(Wv[i4 * 4 + 3], ws, -1.f, 1.f);
    reinterpret_cast<int4*>(Q)[i4] = o;
}

// ---------------- 4) per-token act_quant of x ----------------
__global__ void k_actq1(const float* __restrict__ x) {
    __shared__ float red[256];
    int t = blockIdx.x;
    const float4* px = reinterpret_cast<const float4*>(x + (size_t)t * H_DIM);
    float4 v0 = px[threadIdx.x * 2], v1 = px[threadIdx.x * 2 + 1];
    float m = fmaxf(fmaxf(fmaxf(fabsf(v0.x), fabsf(v0.y)), fmaxf(fabsf(v0.z), fabsf(v0.w))),
                    fmaxf(fmaxf(fabsf(v1.x), fabsf(v1.y)), fmaxf(fabsf(v1.z), fabsf(v1.w))));
    red[threadIdx.x] = m;
    __syncthreads();
    for (int o = 128; o > 0; o >>= 1) {
        if (threadIdx.x < o) red[threadIdx.x] = fmaxf(red[threadIdx.x], red[threadIdx.x + o]);
        __syncthreads();
    }
    float scale = 128.f / fmaxf(red[0], 1e-5f);
    int p0 = pack_q4(v0, scale, -128.f, 127.f);
    int p1 = pack_q4(v1, scale, -128.f, 127.f);
    reinterpret_cast<int2*>(g_xq + (size_t)t * H_DIM)[threadIdx.x] = make_int2(p0, p1);
    if (threadIdx.x == 0) g_xs[t] = scale;
}

// ---------------- GEMM common geometry ----------------
// BM=128, 128 B-rows, BK=64, 8 warps 2(M)x4(N), warp tile 64x32, 5-stage cp.async,
// ldmatrix fragment loads, 256 threads, 2 CTAs/SM.
#define SSTRIDE 80
#define STG_SZ  (128 * SSTRIDE)   // 10240 B per operand per stage
#define NSTG    5
#define DSMEM   (2 * NSTG * STG_SZ)  // 102400 B

// ---------------- 5) GEMM1: IMMA, gate+up interleaved, SiLU epilogue ----------------
__global__ __launch_bounds__(256, 2) void k_gemm1() {
    extern __shared__ signed char dyn[];
    const int tid = threadIdx.x, wid = tid >> 5, lane = tid & 31;
    const int gid = lane >> 2, tig = lane & 3;
    const int wm = wid >> 2, wn = wid & 3;
    const int m0 = blockIdx.y * 128, n0 = blockIdx.x * 64;
    const signed char* A = g_xq + (size_t)m0 * H_DIM;

    const int rowA = (lane & 7) + ((lane >> 3) & 1) * 8;
    const int bytA = ((lane >> 4) & 1) * 16;
    const int rowB = (lane & 7) + ((lane >> 4) & 1) * 8;
    const int bytB = ((lane >> 3) & 1) * 16;
    const uint32_t dynb = smem_u32(dyn);

    int c[4][4][4];
#pragma unroll
    for (int i = 0; i < 4; i++)
#pragma unroll
        for (int j = 0; j < 4; j++)
#pragma unroll
            for (int q = 0; q < 4; q++) c[i][j][q] = 0;

    auto load_stage = [&](int st, int kb) {
        int koff = kb * 64;
        signed char* dA = dyn + st * STG_SZ;
        signed char* dB = dyn + NSTG * STG_SZ + st * STG_SZ;
#pragma unroll
        for (int l = 0; l < 2; l++) {
            int ch = tid + l * 256;
            int r = ch >> 2, c16 = ch & 3;
            CP_ASYNC16(smem_u32(&dA[r * SSTRIDE + c16 * 16]),
                       A + (size_t)r * H_DIM + koff + c16 * 16);
            int n = n0 + (r >> 1);
            const signed char* W = (r & 1) ? g_wqu : g_wqg;
            CP_ASYNC16(smem_u32(&dB[r * SSTRIDE + c16 * 16]),
                       W + (size_t)n * H_DIM + koff + c16 * 16);
        }
    };

    load_stage(0, 0); CP_COMMIT();
    load_stage(1, 1); CP_COMMIT();
    load_stage(2, 2); CP_COMMIT();
    load_stage(3, 3); CP_COMMIT();

    const int NKB = 32;
    for (int kb = 0; kb < NKB; kb++) {
        int rem = NKB - 1 - kb;          // loads still outstanding beyond this one
        if (rem >= 3)      { CP_WAIT(3); }
        else if (rem == 2) { CP_WAIT(2); }
        else if (rem == 1) { CP_WAIT(1); }
        else               { CP_WAIT(0); }
        __syncthreads();
        if (kb + 4 < NKB) { load_stage((kb + 4) % NSTG, kb + 4); CP_COMMIT(); }
        int st = kb % NSTG;
        uint32_t As = dynb + st * STG_SZ;
        uint32_t Bs = dynb + NSTG * STG_SZ + st * STG_SZ;
#pragma unroll
        for (int ks = 0; ks < 2; ks++) {
            int a[4][4], b[4][2];
#pragma unroll
            for (int mi = 0; mi < 4; mi++) {
                uint32_t ad = As + (uint32_t)(wm * 64 + mi * 16 + rowA) * SSTRIDE + ks * 32 + bytA;
                LDSM_X4(a[mi][0], a[mi][1], a[mi][2], a[mi][3], ad);
            }
#pragma unroll
            for (int np = 0; np < 2; np++) {
                uint32_t bd = Bs + (uint32_t)(wn * 32 + np * 16 + rowB) * SSTRIDE + ks * 32 + bytB;
                LDSM_X4(b[2 * np][0], b[2 * np][1], b[2 * np + 1][0], b[2 * np + 1][1], bd);
            }
#pragma unroll
            for (int mi = 0; mi < 4; mi++)
#pragma unroll
                for (int ni = 0; ni < 4; ni++) MMA_S8(c[mi][ni], a[mi], b[ni]);
        }
    }

    // ---- epilogue: stage 128x64 fp32 tile in smem, then coalesced stores ----
    __syncthreads();  // all stages consumed; reuse dyn
    float* sOut = reinterpret_cast<float*>(dyn);  // [128][65] floats = 33280 B
    float fg = g_wnorm[0], fu = g_wnorm[1];
#pragma unroll
    for (int mi = 0; mi < 4; mi++) {
        int r1 = wm * 64 + mi * 16 + gid, r2 = r1 + 8;
        float i1 = 1.0f / g_xs[m0 + r1], i2 = 1.0f / g_xs[m0 + r2];
#pragma unroll
        for (int ni = 0; ni < 4; ni++) {
            int n = wn * 16 + ni * 4 + tig;
            float gv1 = (float)c[mi][ni][0] * fg * i1;
            float uv1 = (float)c[mi][ni][1] * fu * i1;
            sOut[r1 * 65 + n] = gv1 / (1.0f + __expf(-gv1)) * uv1;
            float gv2 = (float)c[mi][ni][2] * fg * i2;
            float uv2 = (float)c[mi][ni][3] * fu * i2;
            sOut[r2 * 65 + n] = gv2 / (1.0f + __expf(-gv2)) * uv2;
        }
    }
    __syncthreads();
    {
        int r = tid >> 1, half = tid & 1;
        float* dst = g_inter + (size_t)(m0 + r) * I_DIM + n0 + half * 32;
        const float* srcp = sOut + r * 65 + half * 32;
#pragma unroll
        for (int i = 0; i < 8; i++) {
            float4 v = make_float4(srcp[i * 4], srcp[i * 4 + 1], srcp[i * 4 + 2], srcp[i * 4 + 3]);
            reinterpret_cast<float4*>(dst)[i] = v;
        }
    }
}

// ---------------- 6) FWHT-8192 + act_quant #2 (register-chunked) ----------------
__global__ __launch_bounds__(512) void k_fwht() {
    __shared__ float s[8192];
    __shared__ float red[512];
    const int tid = threadIdx.x;
    const int t = blockIdx.x;
    float v[16];
    float4* vv = reinterpret_cast<float4*>(v);

    const float4* src = reinterpret_cast<const float4*>(g_inter + (size_t)t * I_DIM);
#pragma unroll
    for (int i = 0; i < 4; i++) vv[i] = src[tid * 4 + i];
#pragma unroll
    for (int h = 1; h < 16; h <<= 1)
#pragma unroll
        for (int i = 0; i < 16; i++)
            if ((i & h) == 0) {
                float a = v[i], b = v[i + h];
                v[i] = a + b; v[i + h] = a - b;
            }
#pragma unroll
    for (int i = 0; i < 4; i++) reinterpret_cast<float4*>(s)[tid * 4 + i] = vv[i];
    __syncthreads();

    int b2 = (tid & 15) + ((tid >> 4) << 8);
#pragma unroll
    for (int j = 0; j < 16; j++) v[j] = s[b2 + 16 * j];
#pragma unroll
    for (int h = 1; h < 16; h <<= 1)
#pragma unroll
        for (int j = 0; j < 16; j++)
            if ((j & h) == 0) {
                float a = v[j], b = v[j + h];
                v[j] = a + b; v[j + h] = a - b;
            }
#pragma unroll
    for (int j = 0; j < 16; j++) s[b2 + 16 * j] = v[j];
    __syncthreads();

    int b3 = (tid & 255) + ((tid >> 8) << 12);
#pragma unroll
    for (int j = 0; j < 16; j++) v[j] = s[b3 + 256 * j];
#pragma unroll
    for (int h = 1; h < 16; h <<= 1)
#pragma unroll
        for (int j = 0; j < 16; j++)
            if ((j & h) == 0) {
                float a = v[j], b = v[j + h];
                v[j] = a + b; v[j + h] = a - b;
            }
#pragma unroll
    for (int j = 0; j < 16; j++) s[b3 + 256 * j] = v[j];
    __syncthreads();

    const float rn = 1.1048543456039805e-02f;  // 1/sqrt(8192)
    float lo[8], hi[8];
    float m = 0.f;
#pragma unroll
    for (int q = 0; q < 8; q++) {
        float a = s[tid * 8 + q], b = s[tid * 8 + q + 4096];
        float na = (a + b) * rn, nb = (a - b) * rn;
        lo[q] = na; hi[q] = nb;
        m = fmaxf(m, fmaxf(fabsf(na), fabsf(nb)));
    }
    red[tid] = m;
    __syncthreads();
    for (int o = 256; o > 0; o >>= 1) {
        if (tid < o) red[tid] = fmaxf(red[tid], red[tid + o]);
        __syncthreads();
    }
    float scale = 128.f / fmaxf(red[0], 1e-5f);
    float4* lv = reinterpret_cast<float4*>(lo);
    float4* hv = reinterpret_cast<float4*>(hi);
    int2 plo = make_int2(pack_q4(lv[0], scale, -128.f, 127.f),
                         pack_q4(lv[1], scale, -128.f, 127.f));
    int2 phi = make_int2(pack_q4(hv[0], scale, -128.f, 127.f),
                         pack_q4(hv[1], scale, -128.f, 127.f));
    int2* orow = reinterpret_cast<int2*>(g_aq2 + (size_t)t * I_DIM);
    orow[tid] = plo;
    orow[tid + 512] = phi;
    if (tid == 0) g_as2[t] = scale;
}

// ---------------- 7) GEMM2: IMMA down projection ----------------
__global__ __launch_bounds__(256, 2) void k_gemm2(float* __restrict__ out) {
    extern __shared__ signed char dyn[];
    const int tid = threadIdx.x, wid = tid >> 5, lane = tid & 31;
    const int gid = lane >> 2, tig = lane & 3;
    const int wm = wid >> 2, wn = wid & 3;
    const int m0 = blockIdx.y * 128, n0 = blockIdx.x * 128;
    const signed char* A = g_aq2 + (size_t)m0 * I_DIM;
    const signed char* B = g_wqd + (size_t)n0 * I_DIM;

    const int rowA = (lane & 7) + ((lane >> 3) & 1) * 8;
    const int bytA = ((lane >> 4) & 1) * 16;
    const int rowB = (lane & 7) + ((lane >> 4) & 1) * 8;
    const int bytB = ((lane >> 3) & 1) * 16;
    const uint32_t dynb = smem_u32(dyn);

    int c[4][4][4];
#pragma unroll
    for (int i = 0; i < 4; i++)
#pragma unroll
        for (int j = 0; j < 4; j++)
#pragma unroll
            for (int q = 0; q < 4; q++) c[i][j][q] = 0;

    auto load_stage = [&](int st, int kb) {
        int koff = kb * 64;
        signed char* dA = dyn + st * STG_SZ;
        signed char* dB = dyn + NSTG * STG_SZ + st * STG_SZ;
#pragma unroll
        for (int l = 0; l < 2; l++) {
            int ch = tid + l * 256;
            int r = ch >> 2, c16 = ch & 3;
            CP_ASYNC16(smem_u32(&dA[r * SSTRIDE + c16 * 16]),
                       A + (size_t)r * I_DIM + koff + c16 * 16);
            CP_ASYNC16(smem_u32(&dB[r * SSTRIDE + c16 * 16]),
                       B + (size_t)r * I_DIM + koff + c16 * 16);
        }
    };

    load_stage(0, 0); CP_COMMIT();
    load_stage(1, 1); CP_COMMIT();
    load_stage(2, 2); CP_COMMIT();
    load_stage(3, 3); CP_COMMIT();

    const int NKB = 128;
    for (int kb = 0; kb < NKB; kb++) {
        int rem = NKB - 1 - kb;
        if (rem >= 3)      { CP_WAIT(3); }
        else if (rem == 2) { CP_WAIT(2); }
        else if (rem == 1) { CP_WAIT(1); }
        else               { CP_WAIT(0); }
        __syncthreads();
        if (kb + 4 < NKB) { load_stage((kb + 4) % NSTG, kb + 4); CP_COMMIT(); }
        int st = kb % NSTG;
        uint32_t As = dynb + st * STG_SZ;
        uint32_t Bs = dynb + NSTG * STG_SZ + st * STG_SZ;
#pragma unroll
        for (int ks = 0; ks < 2; ks++) {
            int a[4][4], b[4][2];
#pragma unroll
            for (int mi = 0; mi < 4; mi++) {
                uint32_t ad = As + (uint32_t)(wm * 64 + mi * 16 + rowA) * SSTRIDE + ks * 32 + bytA;
                LDSM_X4(a[mi][0], a[mi][1], a[mi][2], a[mi][3], ad);
            }
#pragma unroll
            for (int np = 0; np < 2; np++) {
                uint32_t bd = Bs + (uint32_t)(wn * 32 + np * 16 + rowB) * SSTRIDE + ks * 32 + bytB;
                LDSM_X4(b[2 * np][0], b[2 * np][1], b[2 * np + 1][0], b[2 * np + 1][1], bd);
            }
#pragma unroll
            for (int mi = 0; mi < 4; mi++)
#pragma unroll
                for (int ni = 0; ni < 4; ni++) MMA_S8(c[mi][ni], a[mi], b[ni]);
        }
    }

    float fw = g_wnorm[2];
#pragma unroll
    for (int mi = 0; mi < 4; mi++) {
        int t1 = m0 + wm * 64 + mi * 16 + gid, t2 = t1 + 8;
        float f1 = fw / g_as2[t1], f2 = fw / g_as2[t2];
#pragma unroll
        for (int ni = 0; ni < 4; ni++) {
            int col = n0 + wn * 32 + ni * 8 + tig * 2;
            float2 o1 = make_float2((float)c[mi][ni][0] * f1, (float)c[mi][ni][1] * f1);
            float2 o2 = make_float2((float)c[mi][ni][2] * f2, (float)c[mi][ni][3] * f2);
            *reinterpret_cast<float2*>(&out[(size_t)t1 * H_DIM + col]) = o1;
            *reinterpret_cast<float2*>(&out[(size_t)t2 * H_DIM + col]) = o2;
        }
    }
}

// ---------------- launch ----------------
extern "C" void kernel_launch(void* const* d_in, const int* in_sizes, int n_in,
                              void* d_out, int out_size) {
    const float* x  = (const float*)d_in[0];
    const float* wg = (const float*)d_in[1];
    const float* wu = (const float*)d_in[2];
    const float* wd = (const float*)d_in[3];
    float* out = (float*)d_out;

    static int configured = 0;
    if (!configured) {
        cudaFuncSetAttribute(k_gemm1, cudaFuncAttributeMaxDynamicSharedMemorySize, DSMEM);
        cudaFuncSetAttribute(k_gemm2, cudaFuncAttributeMaxDynamicSharedMemorySize, DSMEM);
        configured = 1;
    }

    k_wabs<<<dim3(1024, 3), 256>>>(wg, wu, wd);
    k_wfin<<<3, 1024>>>();
    k_wquant<<<dim3(4096, 3), 256>>>(wg, wu, wd);
    k_actq1<<<T_TOK, 256>>>(x);
    k_gemm1<<<dim3(I_DIM / 64, T_TOK / 128), 256, DSMEM>>>();
    k_fwht<<<T_TOK, 512>>>();
    k_gemm2<<<dim3(H_DIM / 128, T_TOK / 128), 256, DSMEM>>>(out);
}

// round 9
// speedup vs baseline: 1.1250x; 1.0037x over previous
#include <cuda_runtime.h>
#include <cuda_bf16.h>
#include <cstdint>

#define T_TOK 8192
#define H_DIM 2048
#define I_DIM 8192
#define NW    16777216

// ---------------- device scratch ----------------
__device__ float       g_part[3 * 1024];
__device__ float       g_wnorm[3];
__device__ signed char g_wqg[NW];
__device__ signed char g_wqu[NW];
__device__ signed char g_wqd[NW];
__device__ signed char g_xq[T_TOK * H_DIM];
__device__ float       g_xs[T_TOK];
__device__ float       g_inter[67108864];   // fp32 silu(gate)*up [T,I]
__device__ signed char g_aq2[67108864];     // int8 quantized fwht(inter)
__device__ float       g_as2[T_TOK];

// ---------------- helpers ----------------
__device__ __forceinline__ uint32_t smem_u32(const void* p) {
    uint32_t a;
    asm("{ .reg .u64 t; cvta.to.shared.u64 t, %1; cvt.u32.u64 %0, t; }" : "=r"(a) : "l"(p));
    return a;
}
#define CP_ASYNC16(dst, src) \
    asm volatile("cp.async.cg.shared.global [%0], [%1], 16;" :: "r"(dst), "l"(src) : "memory")
#define CP_COMMIT() asm volatile("cp.async.commit_group;" ::: "memory")
#define CP_WAIT(n)  asm volatile("cp.async.wait_group %0;" :: "n"(n) : "memory")

#define MMA_S8(C, A, B) \
    asm volatile("mma.sync.aligned.m16n8k32.row.col.s32.s8.s8.s32 " \
        "{%0,%1,%2,%3}, {%4,%5,%6,%7}, {%8,%9}, {%0,%1,%2,%3};" \
        : "+r"((C)[0]), "+r"((C)[1]), "+r"((C)[2]), "+r"((C)[3]) \
        : "r"((A)[0]), "r"((A)[1]), "r"((A)[2]), "r"((A)[3]), "r"((B)[0]), "r"((B)[1]))

#define LDSM_X4(R0, R1, R2, R3, addr) \
    asm volatile("ldmatrix.sync.aligned.m8n8.x4.shared.b16 {%0,%1,%2,%3}, [%4];" \
        : "=r"(R0), "=r"(R1), "=r"(R2), "=r"(R3) : "r"(addr))

__device__ __forceinline__ int pack_q4(float4 v, float s, float lo, float hi) {
    int q0 = (int)fminf(fmaxf(rintf(v.x * s), lo), hi);
    int q1 = (int)fminf(fmaxf(rintf(v.y * s), lo), hi);
    int q2 = (int)fminf(fmaxf(rintf(v.z * s), lo), hi);
    int q3 = (int)fminf(fmaxf(rintf(v.w * s), lo), hi);
    return (q0 & 0xff) | ((q1 & 0xff) << 8) | ((q2 & 0xff) << 16) | ((q3 & 0xff) << 24);
}

// ---------------- 1) |w| partial reduction ----------------
__global__ void k_wabs(const float* __restrict__ w0, const float* __restrict__ w1,
                       const float* __restrict__ w2) {
    __shared__ float red[256];
    const float* W = (blockIdx.y == 0) ? w0 : ((blockIdx.y == 1) ? w1 : w2);
    float s = 0.f;
    for (int idx = blockIdx.x * 256 + threadIdx.x; idx < NW / 4; idx += 1024 * 256) {
        float4 v = reinterpret_cast<const float4*>(W)[idx];
        s += fabsf(v.x) + fabsf(v.y) + fabsf(v.z) + fabsf(v.w);
    }
    red[threadIdx.x] = s;
    __syncthreads();
    for (int o = 128; o > 0; o >>= 1) {
        if (threadIdx.x < o) red[threadIdx.x] += red[threadIdx.x + o];
        __syncthreads();
    }
    if (threadIdx.x == 0) g_part[blockIdx.y * 1024 + blockIdx.x] = red[0];
}

// ---------------- 2) finalize mean|w| ----------------
__global__ void k_wfin() {
    __shared__ float red[1024];
    int m = blockIdx.x;
    red[threadIdx.x] = g_part[m * 1024 + threadIdx.x];
    __syncthreads();
    for (int o = 512; o > 0; o >>= 1) {
        if (threadIdx.x < o) red[threadIdx.x] += red[threadIdx.x + o];
        __syncthreads();
    }
    if (threadIdx.x == 0) g_wnorm[m] = fmaxf(red[0] / (float)NW, 1e-5f);
}

// ---------------- 3) ternarize weights ----------------
__global__ void k_wquant(const float* __restrict__ w0, const float* __restrict__ w1,
                         const float* __restrict__ w2) {
    int m = blockIdx.y;
    const float* W = (m == 0) ? w0 : ((m == 1) ? w1 : w2);
    signed char* Q = (m == 0) ? g_wqg : ((m == 1) ? g_wqu : g_wqd);
    float ws = 1.0f / g_wnorm[m];
    int i4 = blockIdx.x * 256 + threadIdx.x;
    const float4* Wv = reinterpret_cast<const float4*>(W);
    int4 o;
    o.x = pack_q4(Wv[i4 * 4 + 0], ws, -1.f, 1.f);
    o.y = pack_q4(Wv[i4 * 4 + 1], ws, -1.f, 1.f);
    o.z = pack_q4(Wv[i4 * 4 + 2], ws, -1.f, 1.f);
    o.w = pack_q4(Wv[i4 * 4 + 3], ws, -1.f, 1.f);
    reinterpret_cast<int4*>(Q)[i4] = o;
}

// ---------------- 4) per-token act_quant of x ----------------
__global__ void k_actq1(const float* __restrict__ x) {
    __shared__ float red[256];
    int t = blockIdx.x;
    const float4* px = reinterpret_cast<const float4*>(x + (size_t)t * H_DIM);
    float4 v0 = px[threadIdx.x * 2], v1 = px[threadIdx.x * 2 + 1];
    float m = fmaxf(fmaxf(fmaxf(fabsf(v0.x), fabsf(v0.y)), fmaxf(fabsf(v0.z), fabsf(v0.w))),
                    fmaxf(fmaxf(fabsf(v1.x), fabsf(v1.y)), fmaxf(fabsf(v1.z), fabsf(v1.w))));
    red[threadIdx.x] = m;
    __syncthreads();
    for (int o = 128; o > 0; o >>= 1) {
        if (threadIdx.x < o) red[threadIdx.x] = fmaxf(red[threadIdx.x], red[threadIdx.x + o]);
        __syncthreads();
    }
    float scale = 128.f / fmaxf(red[0], 1e-5f);
    int p0 = pack_q4(v0, scale, -128.f, 127.f);
    int p1 = pack_q4(v1, scale, -128.f, 127.f);
    reinterpret_cast<int2*>(g_xq + (size_t)t * H_DIM)[threadIdx.x] = make_int2(p0, p1);
    if (threadIdx.x == 0) g_xs[t] = scale;
}

// ---------------- GEMM common geometry (R6 known-good) ----------------
// BM=128, 128 B-rows, BK=64, 8 warps 2(M)x4(N), warp tile 64x32, 4-stage cp.async,
// ldmatrix fragment loads, 256 threads, 2 CTAs/SM.
#define SSTRIDE 80
#define STG_SZ  (128 * SSTRIDE)   // 10240 B per operand per stage
#define NSTG    4
#define DSMEM   (2 * NSTG * STG_SZ)  // 81920 B

// ---------------- 5) GEMM1: IMMA, gate+up interleaved, SiLU epilogue ----------------
__global__ __launch_bounds__(256, 2) void k_gemm1() {
    extern __shared__ signed char dyn[];
    const int tid = threadIdx.x, wid = tid >> 5, lane = tid & 31;
    const int gid = lane >> 2, tig = lane & 3;
    const int wm = wid >> 2, wn = wid & 3;
    const int m0 = blockIdx.y * 128, n0 = blockIdx.x * 64;
    const signed char* A = g_xq + (size_t)m0 * H_DIM;

    const int rowA = (lane & 7) + ((lane >> 3) & 1) * 8;
    const int bytA = ((lane >> 4) & 1) * 16;
    const int rowB = (lane & 7) + ((lane >> 4) & 1) * 8;
    const int bytB = ((lane >> 3) & 1) * 16;
    const uint32_t dynb = smem_u32(dyn);

    int c[4][4][4];
#pragma unroll
    for (int i = 0; i < 4; i++)
#pragma unroll
        for (int j = 0; j < 4; j++)
#pragma unroll
            for (int q = 0; q < 4; q++) c[i][j][q] = 0;

    auto load_stage = [&](int st, int kb) {
        int koff = kb * 64;
        signed char* dA = dyn + st * STG_SZ;
        signed char* dB = dyn + NSTG * STG_SZ + st * STG_SZ;
#pragma unroll
        for (int l = 0; l < 2; l++) {
            int ch = tid + l * 256;
            int r = ch >> 2, c16 = ch & 3;
            CP_ASYNC16(smem_u32(&dA[r * SSTRIDE + c16 * 16]),
                       A + (size_t)r * H_DIM + koff + c16 * 16);
            int n = n0 + (r >> 1);
            const signed char* W = (r & 1) ? g_wqu : g_wqg;
            CP_ASYNC16(smem_u32(&dB[r * SSTRIDE + c16 * 16]),
                       W + (size_t)n * H_DIM + koff + c16 * 16);
        }
    };

    load_stage(0, 0); CP_COMMIT();
    load_stage(1, 1); CP_COMMIT();
    load_stage(2, 2); CP_COMMIT();

    const int NKB = 32;
    for (int kb = 0; kb < NKB; kb++) {
        if (kb < NKB - 2)      { CP_WAIT(2); }
        else if (kb == NKB - 2){ CP_WAIT(1); }
        else                   { CP_WAIT(0); }
        __syncthreads();
        if (kb + 3 < NKB) { load_stage((kb + 3) & 3, kb + 3); CP_COMMIT(); }
        int st = kb & 3;
        uint32_t As = dynb + st * STG_SZ;
        uint32_t Bs = dynb + NSTG * STG_SZ + st * STG_SZ;
#pragma unroll
        for (int ks = 0; ks < 2; ks++) {
            int a[4][4], b[4][2];
#pragma unroll
            for (int mi = 0; mi < 4; mi++) {
                uint32_t ad = As + (uint32_t)(wm * 64 + mi * 16 + rowA) * SSTRIDE + ks * 32 + bytA;
                LDSM_X4(a[mi][0], a[mi][1], a[mi][2], a[mi][3], ad);
            }
#pragma unroll
            for (int np = 0; np < 2; np++) {
                uint32_t bd = Bs + (uint32_t)(wn * 32 + np * 16 + rowB) * SSTRIDE + ks * 32 + bytB;
                LDSM_X4(b[2 * np][0], b[2 * np][1], b[2 * np + 1][0], b[2 * np + 1][1], bd);
            }
#pragma unroll
            for (int mi = 0; mi < 4; mi++)
#pragma unroll
                for (int ni = 0; ni < 4; ni++) MMA_S8(c[mi][ni], a[mi], b[ni]);
        }
    }

    // ---- epilogue: stage 128x64 fp32 tile in smem, then coalesced stores ----
    __syncthreads();  // all stages consumed; reuse dyn (81920 B >= 33280 B)
    float* sOut = reinterpret_cast<float*>(dyn);  // [128][65] floats
    float fg = g_wnorm[0], fu = g_wnorm[1];
#pragma unroll
    for (int mi = 0; mi < 4; mi++) {
        int r1 = wm * 64 + mi * 16 + gid, r2 = r1 + 8;
        float i1 = 1.0f / g_xs[m0 + r1], i2 = 1.0f / g_xs[m0 + r2];
#pragma unroll
        for (int ni = 0; ni < 4; ni++) {
            int n = wn * 16 + ni * 4 + tig;
            float gv1 = (float)c[mi][ni][0] * fg * i1;
            float uv1 = (float)c[mi][ni][1] * fu * i1;
            sOut[r1 * 65 + n] = gv1 / (1.0f + __expf(-gv1)) * uv1;
            float gv2 = (float)c[mi][ni][2] * fg * i2;
            float uv2 = (float)c[mi][ni][3] * fu * i2;
            sOut[r2 * 65 + n] = gv2 / (1.0f + __expf(-gv2)) * uv2;
        }
    }
    __syncthreads();
    {
        int r = tid >> 1, half = tid & 1;
        float* dst = g_inter + (size_t)(m0 + r) * I_DIM + n0 + half * 32;
        const float* srcp = sOut + r * 65 + half * 32;
#pragma unroll
        for (int i = 0; i < 8; i++) {
            float4 v = make_float4(srcp[i * 4], srcp[i * 4 + 1], srcp[i * 4 + 2], srcp[i * 4 + 3]);
            reinterpret_cast<float4*>(dst)[i] = v;
        }
    }
}

// ---------------- 6) FWHT-8192 + act_quant #2 (register-chunked) ----------------
__global__ __launch_bounds__(512) void k_fwht() {
    __shared__ float s[8192];
    __shared__ float red[512];
    const int tid = threadIdx.x;
    const int t = blockIdx.x;
    float v[16];
    float4* vv = reinterpret_cast<float4*>(v);

    const float4* src = reinterpret_cast<const float4*>(g_inter + (size_t)t * I_DIM);
#pragma unroll
    for (int i = 0; i < 4; i++) vv[i] = src[tid * 4 + i];
#pragma unroll
    for (int h = 1; h < 16; h <<= 1)
#pragma unroll
        for (int i = 0; i < 16; i++)
            if ((i & h) == 0) {
                float a = v[i], b = v[i + h];
                v[i] = a + b; v[i + h] = a - b;
            }
#pragma unroll
    for (int i = 0; i < 4; i++) reinterpret_cast<float4*>(s)[tid * 4 + i] = vv[i];
    __syncthreads();

    int b2 = (tid & 15) + ((tid >> 4) << 8);
#pragma unroll
    for (int j = 0; j < 16; j++) v[j] = s[b2 + 16 * j];
#pragma unroll
    for (int h = 1; h < 16; h <<= 1)
#pragma unroll
        for (int j = 0; j < 16; j++)
            if ((j & h) == 0) {
                float a = v[j], b = v[j + h];
                v[j] = a + b; v[j + h] = a - b;
            }
#pragma unroll
    for (int j = 0; j < 16; j++) s[b2 + 16 * j] = v[j];
    __syncthreads();

    int b3 = (tid & 255) + ((tid >> 8) << 12);
#pragma unroll
    for (int j = 0; j < 16; j++) v[j] = s[b3 + 256 * j];
#pragma unroll
    for (int h = 1; h < 16; h <<= 1)
#pragma unroll
        for (int j = 0; j < 16; j++)
            if ((j & h) == 0) {
                float a = v[j], b = v[j + h];
                v[j] = a + b; v[j + h] = a - b;
            }
#pragma unroll
    for (int j = 0; j < 16; j++) s[b3 + 256 * j] = v[j];
    __syncthreads();

    const float rn = 1.1048543456039805e-02f;  // 1/sqrt(8192)
    float lo[8], hi[8];
    float m = 0.f;
#pragma unroll
    for (int q = 0; q < 8; q++) {
        float a = s[tid * 8 + q], b = s[tid * 8 + q + 4096];
        float na = (a + b) * rn, nb = (a - b) * rn;
        lo[q] = na; hi[q] = nb;
        m = fmaxf(m, fmaxf(fabsf(na), fabsf(nb)));
    }
    red[tid] = m;
    __syncthreads();
    for (int o = 256; o > 0; o >>= 1) {
        if (tid < o) red[tid] = fmaxf(red[tid], red[tid + o]);
        __syncthreads();
    }
    float scale = 128.f / fmaxf(red[0], 1e-5f);
    float4* lv = reinterpret_cast<float4*>(lo);
    float4* hv = reinterpret_cast<float4*>(hi);
    int2 plo = make_int2(pack_q4(lv[0], scale, -128.f, 127.f),
                         pack_q4(lv[1], scale, -128.f, 127.f));
    int2 phi = make_int2(pack_q4(hv[0], scale, -128.f, 127.f),
                         pack_q4(hv[1], scale, -128.f, 127.f));
    int2* orow = reinterpret_cast<int2*>(g_aq2 + (size_t)t * I_DIM);
    orow[tid] = plo;
    orow[tid + 512] = phi;
    if (tid == 0) g_as2[t] = scale;
}

// ---------------- 7) GEMM2: IMMA down projection ----------------
__global__ __launch_bounds__(256, 2) void k_gemm2(float* __restrict__ out) {
    extern __shared__ signed char dyn[];
    const int tid = threadIdx.x, wid = tid >> 5, lane = tid & 31;
    const int gid = lane >> 2, tig = lane & 3;
    const int wm = wid >> 2, wn = wid & 3;
    const int m0 = blockIdx.y * 128, n0 = blockIdx.x * 128;
    const signed char* A = g_aq2 + (size_t)m0 * I_DIM;
    const signed char* B = g_wqd + (size_t)n0 * I_DIM;

    const int rowA = (lane & 7) + ((lane >> 3) & 1) * 8;
    const int bytA = ((lane >> 4) & 1) * 16;
    const int rowB = (lane & 7) + ((lane >> 4) & 1) * 8;
    const int bytB = ((lane >> 3) & 1) * 16;
    const uint32_t dynb = smem_u32(dyn);

    int c[4][4][4];
#pragma unroll
    for (int i = 0; i < 4; i++)
#pragma unroll
        for (int j = 0; j < 4; j++)
#pragma unroll
            for (int q = 0; q < 4; q++) c[i][j][q] = 0;

    auto load_stage = [&](int st, int kb) {
        int koff = kb * 64;
        signed char* dA = dyn + st * STG_SZ;
        signed char* dB = dyn + NSTG * STG_SZ + st * STG_SZ;
#pragma unroll
        for (int l = 0; l < 2; l++) {
            int ch = tid + l * 256;
            int r = ch >> 2, c16 = ch & 3;
            CP_ASYNC16(smem_u32(&dA[r * SSTRIDE + c16 * 16]),
                       A + (size_t)r * I_DIM + koff + c16 * 16);
            CP_ASYNC16(smem_u32(&dB[r * SSTRIDE + c16 * 16]),
                       B + (size_t)r * I_DIM + koff + c16 * 16);
        }
    };

    load_stage(0, 0); CP_COMMIT();
    load_stage(1, 1); CP_COMMIT();
    load_stage(2, 2); CP_COMMIT();

    const int NKB = 128;
    for (int kb = 0; kb < NKB; kb++) {
        if (kb < NKB - 2)      { CP_WAIT(2); }
        else if (kb == NKB - 2){ CP_WAIT(1); }
        else                   { CP_WAIT(0); }
        __syncthreads();
        if (kb + 3 < NKB) { load_stage((kb + 3) & 3, kb + 3); CP_COMMIT(); }
        int st = kb & 3;
        uint32_t As = dynb + st * STG_SZ;
        uint32_t Bs = dynb + NSTG * STG_SZ + st * STG_SZ;
#pragma unroll
        for (int ks = 0; ks < 2; ks++) {
            int a[4][4], b[4][2];
#pragma unroll
            for (int mi = 0; mi < 4; mi++) {
                uint32_t ad = As + (uint32_t)(wm * 64 + mi * 16 + rowA) * SSTRIDE + ks * 32 + bytA;
                LDSM_X4(a[mi][0], a[mi][1], a[mi][2], a[mi][3], ad);
            }
#pragma unroll
            for (int np = 0; np < 2; np++) {
                uint32_t bd = Bs + (uint32_t)(wn * 32 + np * 16 + rowB) * SSTRIDE + ks * 32 + bytB;
                LDSM_X4(b[2 * np][0], b[2 * np][1], b[2 * np + 1][0], b[2 * np + 1][1], bd);
            }
#pragma unroll
            for (int mi = 0; mi < 4; mi++)
#pragma unroll
                for (int ni = 0; ni < 4; ni++) MMA_S8(c[mi][ni], a[mi], b[ni]);
        }
    }

    float fw = g_wnorm[2];
#pragma unroll
    for (int mi = 0; mi < 4; mi++) {
        int t1 = m0 + wm * 64 + mi * 16 + gid, t2 = t1 + 8;
        float f1 = fw / g_as2[t1], f2 = fw / g_as2[t2];
#pragma unroll
        for (int ni = 0; ni < 4; ni++) {
            int col = n0 + wn * 32 + ni * 8 + tig * 2;
            float2 o1 = make_float2((float)c[mi][ni][0] * f1, (float)c[mi][ni][1] * f1);
            float2 o2 = make_float2((float)c[mi][ni][2] * f2, (float)c[mi][ni][3] * f2);
            *reinterpret_cast<float2*>(&out[(size_t)t1 * H_DIM + col]) = o1;
            *reinterpret_cast<float2*>(&out[(size_t)t2 * H_DIM + col]) = o2;
        }
    }
}

// ---------------- launch ----------------
extern "C" void kernel_launch(void* const* d_in, const int* in_sizes, int n_in,
                              void* d_out, int out_size) {
    const float* x  = (const float*)d_in[0];
    const float* wg = (const float*)d_in[1];
    const float* wu = (const float*)d_in[2];
    const float* wd = (const float*)d_in[3];
    float* out = (float*)d_out;

    static int configured = 0;
    if (!configured) {
        cudaFuncSetAttribute(k_gemm1, cudaFuncAttributeMaxDynamicSharedMemorySize, DSMEM);
        cudaFuncSetAttribute(k_gemm2, cudaFuncAttributeMaxDynamicSharedMemorySize, DSMEM);
        configured = 1;
    }

    k_wabs<<<dim3(1024, 3), 256>>>(wg, wu, wd);
    k_wfin<<<3, 1024>>>();
    k_wquant<<<dim3(4096, 3), 256>>>(wg, wu, wd);
    k_actq1<<<T_TOK, 256>>>(x);
    k_gemm1<<<dim3(I_DIM / 64, T_TOK / 128), 256, DSMEM>>>();
    k_fwht<<<T_TOK, 512>>>();
    k_gemm2<<<dim3(H_DIM / 128, T_TOK / 128), 256, DSMEM>>>(out);
}

// round 10
// speedup vs baseline: 1.1575x; 1.0289x over previous
#include <cuda_runtime.h>
#include <cuda_bf16.h>
#include <cstdint>

#define T_TOK 8192
#define H_DIM 2048
#define I_DIM 8192
#define NW    16777216

// ---------------- device scratch ----------------
__device__ float       g_part[3 * 1024];
__device__ float       g_wnorm[3];
__device__ signed char g_wqg[NW];
__device__ signed char g_wqu[NW];
__device__ signed char g_wqd[NW];
__device__ signed char g_xq[T_TOK * H_DIM];
__device__ float       g_xs[T_TOK];
__device__ float       g_inter[67108864];   // fp32 silu(gate)*up [T,I]
__device__ signed char g_aq2[67108864];     // int8 quantized fwht(inter)
__device__ float       g_as2[T_TOK];

// ---------------- helpers ----------------
__device__ __forceinline__ uint32_t smem_u32(const void* p) {
    uint32_t a;
    asm("{ .reg .u64 t; cvta.to.shared.u64 t, %1; cvt.u32.u64 %0, t; }" : "=r"(a) : "l"(p));
    return a;
}
#define CP_ASYNC16(dst, src) \
    asm volatile("cp.async.cg.shared.global [%0], [%1], 16;" :: "r"(dst), "l"(src) : "memory")
#define CP_COMMIT() asm volatile("cp.async.commit_group;" ::: "memory")
#define CP_WAIT(n)  asm volatile("cp.async.wait_group %0;" :: "n"(n) : "memory")

#define MMA_S8(C, A, B) \
    asm volatile("mma.sync.aligned.m16n8k32.row.col.s32.s8.s8.s32 " \
        "{%0,%1,%2,%3}, {%4,%5,%6,%7}, {%8,%9}, {%0,%1,%2,%3};" \
        : "+r"((C)[0]), "+r"((C)[1]), "+r"((C)[2]), "+r"((C)[3]) \
        : "r"((A)[0]), "r"((A)[1]), "r"((A)[2]), "r"((A)[3]), "r"((B)[0]), "r"((B)[1]))

#define LDSM_X4(R0, R1, R2, R3, addr) \
    asm volatile("ldmatrix.sync.aligned.m8n8.x4.shared.b16 {%0,%1,%2,%3}, [%4];" \
        : "=r"(R0), "=r"(R1), "=r"(R2), "=r"(R3) : "r"(addr))

__device__ __forceinline__ int pack_q4(float4 v, float s, float lo, float hi) {
    int q0 = (int)fminf(fmaxf(rintf(v.x * s), lo), hi);
    int q1 = (int)fminf(fmaxf(rintf(v.y * s), lo), hi);
    int q2 = (int)fminf(fmaxf(rintf(v.z * s), lo), hi);
    int q3 = (int)fminf(fmaxf(rintf(v.w * s), lo), hi);
    return (q0 & 0xff) | ((q1 & 0xff) << 8) | ((q2 & 0xff) << 16) | ((q3 & 0xff) << 24);
}

// ---------------- 1) |w| partial reduction ----------------
__global__ void k_wabs(const float* __restrict__ w0, const float* __restrict__ w1,
                       const float* __restrict__ w2) {
    __shared__ float red[256];
    const float* W = (blockIdx.y == 0) ? w0 : ((blockIdx.y == 1) ? w1 : w2);
    float s = 0.f;
    for (int idx = blockIdx.x * 256 + threadIdx.x; idx < NW / 4; idx += 1024 * 256) {
        float4 v = reinterpret_cast<const float4*>(W)[idx];
        s += fabsf(v.x) + fabsf(v.y) + fabsf(v.z) + fabsf(v.w);
    }
    red[threadIdx.x] = s;
    __syncthreads();
    for (int o = 128; o > 0; o >>= 1) {
        if (threadIdx.x < o) red[threadIdx.x] += red[threadIdx.x + o];
        __syncthreads();
    }
    if (threadIdx.x == 0) g_part[blockIdx.y * 1024 + blockIdx.x] = red[0];
}

// ---------------- 2) finalize mean|w| ----------------
__global__ void k_wfin() {
    __shared__ float red[1024];
    int m = blockIdx.x;
    red[threadIdx.x] = g_part[m * 1024 + threadIdx.x];
    __syncthreads();
    for (int o = 512; o > 0; o >>= 1) {
        if (threadIdx.x < o) red[threadIdx.x] += red[threadIdx.x + o];
        __syncthreads();
    }
    if (threadIdx.x == 0) g_wnorm[m] = fmaxf(red[0] / (float)NW, 1e-5f);
}

// ---------------- 3) ternarize weights (mbase selects matrices) ----------------
__global__ void k_wquant(const float* __restrict__ w0, const float* __restrict__ w1,
                         const float* __restrict__ w2, int mbase) {
    int m = mbase + blockIdx.y;
    const float* W = (m == 0) ? w0 : ((m == 1) ? w1 : w2);
    signed char* Q = (m == 0) ? g_wqg : ((m == 1) ? g_wqu : g_wqd);
    float ws = 1.0f / g_wnorm[m];
    int i4 = blockIdx.x * 256 + threadIdx.x;
    const float4* Wv = reinterpret_cast<const float4*>(W);
    int4 o;
    o.x = pack_q4(Wv[i4 * 4 + 0], ws, -1.f, 1.f);
    o.y = pack_q4(Wv[i4 * 4 + 1], ws, -1.f, 1.f);
    o.z = pack_q4(Wv[i4 * 4 + 2], ws, -1.f, 1.f);
    o.w = pack_q4(Wv[i4 * 4 + 3], ws, -1.f, 1.f);
    reinterpret_cast<int4*>(Q)[i4] = o;
}

// ---------------- 4) per-token act_quant of x ----------------
__global__ void k_actq1(const float* __restrict__ x) {
    __shared__ float red[256];
    int t = blockIdx.x;
    const float4* px = reinterpret_cast<const float4*>(x + (size_t)t * H_DIM);
    float4 v0 = px[threadIdx.x * 2], v1 = px[threadIdx.x * 2 + 1];
    float m = fmaxf(fmaxf(fmaxf(fabsf(v0.x), fabsf(v0.y)), fmaxf(fabsf(v0.z), fabsf(v0.w))),
                    fmaxf(fmaxf(fabsf(v1.x), fabsf(v1.y)), fmaxf(fabsf(v1.z), fabsf(v1.w))));
    red[threadIdx.x] = m;
    __syncthreads();
    for (int o = 128; o > 0; o >>= 1) {
        if (threadIdx.x < o) red[threadIdx.x] = fmaxf(red[threadIdx.x], red[threadIdx.x + o]);
        __syncthreads();
    }
    float scale = 128.f / fmaxf(red[0], 1e-5f);
    int p0 = pack_q4(v0, scale, -128.f, 127.f);
    int p1 = pack_q4(v1, scale, -128.f, 127.f);
    reinterpret_cast<int2*>(g_xq + (size_t)t * H_DIM)[threadIdx.x] = make_int2(p0, p1);
    if (threadIdx.x == 0) g_xs[t] = scale;
}

// ---------------- GEMM common geometry (R6 known-good) ----------------
#define SSTRIDE 80
#define STG_SZ  (128 * SSTRIDE)
#define NSTG    4
#define DSMEM   (2 * NSTG * STG_SZ)  // 81920 B

// ---------------- 5) GEMM1: IMMA, gate+up interleaved, SiLU epilogue ----------------
__global__ __launch_bounds__(256, 2) void k_gemm1() {
    extern __shared__ signed char dyn[];
    const int tid = threadIdx.x, wid = tid >> 5, lane = tid & 31;
    const int gid = lane >> 2, tig = lane & 3;
    const int wm = wid >> 2, wn = wid & 3;
    const int m0 = blockIdx.y * 128, n0 = blockIdx.x * 64;
    const signed char* A = g_xq + (size_t)m0 * H_DIM;

    const int rowA = (lane & 7) + ((lane >> 3) & 1) * 8;
    const int bytA = ((lane >> 4) & 1) * 16;
    const int rowB = (lane & 7) + ((lane >> 4) & 1) * 8;
    const int bytB = ((lane >> 3) & 1) * 16;
    const uint32_t dynb = smem_u32(dyn);

    int c[4][4][4];
#pragma unroll
    for (int i = 0; i < 4; i++)
#pragma unroll
        for (int j = 0; j < 4; j++)
#pragma unroll
            for (int q = 0; q < 4; q++) c[i][j][q] = 0;

    auto load_stage = [&](int st, int kb) {
        int koff = kb * 64;
        signed char* dA = dyn + st * STG_SZ;
        signed char* dB = dyn + NSTG * STG_SZ + st * STG_SZ;
#pragma unroll
        for (int l = 0; l < 2; l++) {
            int ch = tid + l * 256;
            int r = ch >> 2, c16 = ch & 3;
            CP_ASYNC16(smem_u32(&dA[r * SSTRIDE + c16 * 16]),
                       A + (size_t)r * H_DIM + koff + c16 * 16);
            int n = n0 + (r >> 1);
            const signed char* W = (r & 1) ? g_wqu : g_wqg;
            CP_ASYNC16(smem_u32(&dB[r * SSTRIDE + c16 * 16]),
                       W + (size_t)n * H_DIM + koff + c16 * 16);
        }
    };

    load_stage(0, 0); CP_COMMIT();
    load_stage(1, 1); CP_COMMIT();
    load_stage(2, 2); CP_COMMIT();

    const int NKB = 32;
    for (int kb = 0; kb < NKB; kb++) {
        if (kb < NKB - 2)      { CP_WAIT(2); }
        else if (kb == NKB - 2){ CP_WAIT(1); }
        else                   { CP_WAIT(0); }
        __syncthreads();
        if (kb + 3 < NKB) { load_stage((kb + 3) & 3, kb + 3); CP_COMMIT(); }
        int st = kb & 3;
        uint32_t As = dynb + st * STG_SZ;
        uint32_t Bs = dynb + NSTG * STG_SZ + st * STG_SZ;
#pragma unroll
        for (int ks = 0; ks < 2; ks++) {
            int a[4][4], b[4][2];
#pragma unroll
            for (int mi = 0; mi < 4; mi++) {
                uint32_t ad = As + (uint32_t)(wm * 64 + mi * 16 + rowA) * SSTRIDE + ks * 32 + bytA;
                LDSM_X4(a[mi][0], a[mi][1], a[mi][2], a[mi][3], ad);
            }
#pragma unroll
            for (int np = 0; np < 2; np++) {
                uint32_t bd = Bs + (uint32_t)(wn * 32 + np * 16 + rowB) * SSTRIDE + ks * 32 + bytB;
                LDSM_X4(b[2 * np][0], b[2 * np][1], b[2 * np + 1][0], b[2 * np + 1][1], bd);
            }
#pragma unroll
            for (int mi = 0; mi < 4; mi++)
#pragma unroll
                for (int ni = 0; ni < 4; ni++) MMA_S8(c[mi][ni], a[mi], b[ni]);
        }
    }

    float fg = g_wnorm[0], fu = g_wnorm[1];
#pragma unroll
    for (int mi = 0; mi < 4; mi++) {
        int t1 = m0 + wm * 64 + mi * 16 + gid, t2 = t1 + 8;
        float i1 = 1.0f / g_xs[t1], i2 = 1.0f / g_xs[t2];
#pragma unroll
        for (int ni = 0; ni < 4; ni++) {
            int n = n0 + wn * 16 + ni * 4 + tig;
            float gv1 = (float)c[mi][ni][0] * fg * i1;
            float uv1 = (float)c[mi][ni][1] * fu * i1;
            g_inter[(size_t)t1 * I_DIM + n] = gv1 / (1.0f + __expf(-gv1)) * uv1;
            float gv2 = (float)c[mi][ni][2] * fg * i2;
            float uv2 = (float)c[mi][ni][3] * fu * i2;
            g_inter[(size_t)t2 * I_DIM + n] = gv2 / (1.0f + __expf(-gv2)) * uv2;
        }
    }
}

// ---------------- 6) FWHT-8192 + act_quant #2 (register-chunked) ----------------
__global__ __launch_bounds__(512) void k_fwht() {
    __shared__ float s[8192];
    __shared__ float red[512];
    const int tid = threadIdx.x;
    const int t = blockIdx.x;
    float v[16];
    float4* vv = reinterpret_cast<float4*>(v);

    const float4* src = reinterpret_cast<const float4*>(g_inter + (size_t)t * I_DIM);
#pragma unroll
    for (int i = 0; i < 4; i++) vv[i] = src[tid * 4 + i];
#pragma unroll
    for (int h = 1; h < 16; h <<= 1)
#pragma unroll
        for (int i = 0; i < 16; i++)
            if ((i & h) == 0) {
                float a = v[i], b = v[i + h];
                v[i] = a + b; v[i + h] = a - b;
            }
#pragma unroll
    for (int i = 0; i < 4; i++) reinterpret_cast<float4*>(s)[tid * 4 + i] = vv[i];
    __syncthreads();

    int b2 = (tid & 15) + ((tid >> 4) << 8);
#pragma unroll
    for (int j = 0; j < 16; j++) v[j] = s[b2 + 16 * j];
#pragma unroll
    for (int h = 1; h < 16; h <<= 1)
#pragma unroll
        for (int j = 0; j < 16; j++)
            if ((j & h) == 0) {
                float a = v[j], b = v[j + h];
                v[j] = a + b; v[j + h] = a - b;
            }
#pragma unroll
    for (int j = 0; j < 16; j++) s[b2 + 16 * j] = v[j];
    __syncthreads();

    int b3 = (tid & 255) + ((tid >> 8) << 12);
#pragma unroll
    for (int j = 0; j < 16; j++) v[j] = s[b3 + 256 * j];
#pragma unroll
    for (int h = 1; h < 16; h <<= 1)
#pragma unroll
        for (int j = 0; j < 16; j++)
            if ((j & h) == 0) {
                float a = v[j], b = v[j + h];
                v[j] = a + b; v[j + h] = a - b;
            }
#pragma unroll
    for (int j = 0; j < 16; j++) s[b3 + 256 * j] = v[j];
    __syncthreads();

    const float rn = 1.1048543456039805e-02f;  // 1/sqrt(8192)
    float lo[8], hi[8];
    float m = 0.f;
#pragma unroll
    for (int q = 0; q < 8; q++) {
        float a = s[tid * 8 + q], b = s[tid * 8 + q + 4096];
        float na = (a + b) * rn, nb = (a - b) * rn;
        lo[q] = na; hi[q] = nb;
        m = fmaxf(m, fmaxf(fabsf(na), fabsf(nb)));
    }
    red[tid] = m;
    __syncthreads();
    for (int o = 256; o > 0; o >>= 1) {
        if (tid < o) red[tid] = fmaxf(red[tid], red[tid + o]);
        __syncthreads();
    }
    float scale = 128.f / fmaxf(red[0], 1e-5f);
    float4* lv = reinterpret_cast<float4*>(lo);
    float4* hv = reinterpret_cast<float4*>(hi);
    int2 plo = make_int2(pack_q4(lv[0], scale, -128.f, 127.f),
                         pack_q4(lv[1], scale, -128.f, 127.f));
    int2 phi = make_int2(pack_q4(hv[0], scale, -128.f, 127.f),
                         pack_q4(hv[1], scale, -128.f, 127.f));
    int2* orow = reinterpret_cast<int2*>(g_aq2 + (size_t)t * I_DIM);
    orow[tid] = plo;
    orow[tid + 512] = phi;
    if (tid == 0) g_as2[t] = scale;
}

// ---------------- 7) GEMM2: IMMA down projection ----------------
__global__ __launch_bounds__(256, 2) void k_gemm2(float* __restrict__ out) {
    extern __shared__ signed char dyn[];
    const int tid = threadIdx.x, wid = tid >> 5, lane = tid & 31;
    const int gid = lane >> 2, tig = lane & 3;
    const int wm = wid >> 2, wn = wid & 3;
    const int m0 = blockIdx.y * 128, n0 = blockIdx.x * 128;
    const signed char* A = g_aq2 + (size_t)m0 * I_DIM;
    const signed char* B = g_wqd + (size_t)n0 * I_DIM;

    const int rowA = (lane & 7) + ((lane >> 3) & 1) * 8;
    const int bytA = ((lane >> 4) & 1) * 16;
    const int rowB = (lane & 7) + ((lane >> 4) & 1) * 8;
    const int bytB = ((lane >> 3) & 1) * 16;
    const uint32_t dynb = smem_u32(dyn);

    int c[4][4][4];
#pragma unroll
    for (int i = 0; i < 4; i++)
#pragma unroll
        for (int j = 0; j < 4; j++)
#pragma unroll
            for (int q = 0; q < 4; q++) c[i][j][q] = 0;

    auto load_stage = [&](int st, int kb) {
        int koff = kb * 64;
        signed char* dA = dyn + st * STG_SZ;
        signed char* dB = dyn + NSTG * STG_SZ + st * STG_SZ;
#pragma unroll
        for (int l = 0; l < 2; l++) {
            int ch = tid + l * 256;
            int r = ch >> 2, c16 = ch & 3;
            CP_ASYNC16(smem_u32(&dA[r * SSTRIDE + c16 * 16]),
                       A + (size_t)r * I_DIM + koff + c16 * 16);
            CP_ASYNC16(smem_u32(&dB[r * SSTRIDE + c16 * 16]),
                       B + (size_t)r * I_DIM + koff + c16 * 16);
        }
    };

    load_stage(0, 0); CP_COMMIT();
    load_stage(1, 1); CP_COMMIT();
    load_stage(2, 2); CP_COMMIT();

    const int NKB = 128;
    for (int kb = 0; kb < NKB; kb++) {
        if (kb < NKB - 2)      { CP_WAIT(2); }
        else if (kb == NKB - 2){ CP_WAIT(1); }
        else                   { CP_WAIT(0); }
        __syncthreads();
        if (kb + 3 < NKB) { load_stage((kb + 3) & 3, kb + 3); CP_COMMIT(); }
        int st = kb & 3;
        uint32_t As = dynb + st * STG_SZ;
        uint32_t Bs = dynb + NSTG * STG_SZ + st * STG_SZ;
#pragma unroll
        for (int ks = 0; ks < 2; ks++) {
            int a[4][4], b[4][2];
#pragma unroll
            for (int mi = 0; mi < 4; mi++) {
                uint32_t ad = As + (uint32_t)(wm * 64 + mi * 16 + rowA) * SSTRIDE + ks * 32 + bytA;
                LDSM_X4(a[mi][0], a[mi][1], a[mi][2], a[mi][3], ad);
            }
#pragma unroll
            for (int np = 0; np < 2; np++) {
                uint32_t bd = Bs + (uint32_t)(wn * 32 + np * 16 + rowB) * SSTRIDE + ks * 32 + bytB;
                LDSM_X4(b[2 * np][0], b[2 * np][1], b[2 * np + 1][0], b[2 * np + 1][1], bd);
            }
#pragma unroll
            for (int mi = 0; mi < 4; mi++)
#pragma unroll
                for (int ni = 0; ni < 4; ni++) MMA_S8(c[mi][ni], a[mi], b[ni]);
        }
    }

    float fw = g_wnorm[2];
#pragma unroll
    for (int mi = 0; mi < 4; mi++) {
        int t1 = m0 + wm * 64 + mi * 16 + gid, t2 = t1 + 8;
        float f1 = fw / g_as2[t1], f2 = fw / g_as2[t2];
#pragma unroll
        for (int ni = 0; ni < 4; ni++) {
            int col = n0 + wn * 32 + ni * 8 + tig * 2;
            float2 o1 = make_float2((float)c[mi][ni][0] * f1, (float)c[mi][ni][1] * f1);
            float2 o2 = make_float2((float)c[mi][ni][2] * f2, (float)c[mi][ni][3] * f2);
            *reinterpret_cast<float2*>(&out[(size_t)t1 * H_DIM + col]) = o1;
            *reinterpret_cast<float2*>(&out[(size_t)t2 * H_DIM + col]) = o2;
        }
    }
}

// ---------------- launch (multi-stream fork/join for graph concurrency) ----------------
extern "C" void kernel_launch(void* const* d_in, const int* in_sizes, int n_in,
                              void* d_out, int out_size) {
    const float* x  = (const float*)d_in[0];
    const float* wg = (const float*)d_in[1];
    const float* wu = (const float*)d_in[2];
    const float* wd = (const float*)d_in[3];
    float* out = (float*)d_out;

    static cudaStream_t s2 = nullptr, s3 = nullptr;
    static cudaEvent_t evRoot = nullptr, evFin = nullptr, evActq = nullptr, evWd = nullptr;
    static int configured = 0;
    if (!configured) {
        cudaFuncSetAttribute(k_gemm1, cudaFuncAttributeMaxDynamicSharedMemorySize, DSMEM);
        cudaFuncSetAttribute(k_gemm2, cudaFuncAttributeMaxDynamicSharedMemorySize, DSMEM);
        cudaStreamCreateWithFlags(&s2, cudaStreamNonBlocking);
        cudaStreamCreateWithFlags(&s3, cudaStreamNonBlocking);
        cudaEventCreateWithFlags(&evRoot, cudaEventDisableTiming);
        cudaEventCreateWithFlags(&evFin,  cudaEventDisableTiming);
        cudaEventCreateWithFlags(&evActq, cudaEventDisableTiming);
        cudaEventCreateWithFlags(&evWd,   cudaEventDisableTiming);
        configured = 1;
    }

    // fork: actq1 (x only) runs concurrent with the weight chain
    cudaEventRecord(evRoot, 0);
    cudaStreamWaitEvent(s2, evRoot, 0);
    k_actq1<<<T_TOK, 256, 0, s2>>>(x);
    cudaEventRecord(evActq, s2);

    // main chain: |w| mean for all three matrices
    k_wabs<<<dim3(1024, 3), 256>>>(wg, wu, wd);
    k_wfin<<<3, 1024>>>();
    cudaEventRecord(evFin, 0);

    // side branch: w_down ternarization, joins before gemm2
    cudaStreamWaitEvent(s3, evFin, 0);
    k_wquant<<<dim3(4096, 1), 256, 0, s3>>>(wg, wu, wd, 2);
    cudaEventRecord(evWd, s3);

    // main: gate+up ternarization, then GEMM1 (joins actq1)
    k_wquant<<<dim3(4096, 2), 256>>>(wg, wu, wd, 0);
    cudaStreamWaitEvent(0, evActq, 0);
    k_gemm1<<<dim3(I_DIM / 64, T_TOK / 128), 256, DSMEM>>>();
    k_fwht<<<T_TOK, 512>>>();
    cudaStreamWaitEvent(0, evWd, 0);
    k_gemm2<<<dim3(H_DIM / 128, T_TOK / 128), 256, DSMEM>>>(out);
}

// round 11
// speedup vs baseline: 1.2617x; 1.0900x over previous
#include <cuda_runtime.h>
#include <cuda_bf16.h>
#include <cstdint>

#define T_TOK 8192
#define H_DIM 2048
#define I_DIM 8192
#define NW    16777216

// ---------------- device scratch ----------------
__device__ float       g_part[3 * 1024];
__device__ float       g_wnorm[3];
__device__ signed char g_wqg[NW];
__device__ signed char g_wqu[NW];
__device__ signed char g_wqd[NW];
__device__ signed char g_xq[T_TOK * H_DIM];
__device__ float       g_xs[T_TOK];
__device__ float       g_inter[67108864];   // fp32 silu(gate)*up [T,I]
__device__ signed char g_aq2[67108864];     // int8 quantized fwht(inter)
__device__ float       g_as2[T_TOK];

// ---------------- helpers ----------------
__device__ __forceinline__ uint32_t smem_u32(const void* p) {
    uint32_t a;
    asm("{ .reg .u64 t; cvta.to.shared.u64 t, %1; cvt.u32.u64 %0, t; }" : "=r"(a) : "l"(p));
    return a;
}
#define CP_ASYNC16(dst, src) \
    asm volatile("cp.async.cg.shared.global [%0], [%1], 16;" :: "r"(dst), "l"(src) : "memory")
#define CP_COMMIT() asm volatile("cp.async.commit_group;" ::: "memory")
#define CP_WAIT(n)  asm volatile("cp.async.wait_group %0;" :: "n"(n) : "memory")

#define MMA_S8(C, A, B) \
    asm volatile("mma.sync.aligned.m16n8k32.row.col.s32.s8.s8.s32 " \
        "{%0,%1,%2,%3}, {%4,%5,%6,%7}, {%8,%9}, {%0,%1,%2,%3};" \
        : "+r"((C)[0]), "+r"((C)[1]), "+r"((C)[2]), "+r"((C)[3]) \
        : "r"((A)[0]), "r"((A)[1]), "r"((A)[2]), "r"((A)[3]), "r"((B)[0]), "r"((B)[1]))

#define LDSM_X4(R0, R1, R2, R3, addr) \
    asm volatile("ldmatrix.sync.aligned.m8n8.x4.shared.b16 {%0,%1,%2,%3}, [%4];" \
        : "=r"(R0), "=r"(R1), "=r"(R2), "=r"(R3) : "r"(addr))

__device__ __forceinline__ int pack_q4(float4 v, float s, float lo, float hi) {
    int q0 = (int)fminf(fmaxf(rintf(v.x * s), lo), hi);
    int q1 = (int)fminf(fmaxf(rintf(v.y * s), lo), hi);
    int q2 = (int)fminf(fmaxf(rintf(v.z * s), lo), hi);
    int q3 = (int)fminf(fmaxf(rintf(v.w * s), lo), hi);
    return (q0 & 0xff) | ((q1 & 0xff) << 8) | ((q2 & 0xff) << 16) | ((q3 & 0xff) << 24);
}

// ---------------- 1) |w| partial reduction ----------------
__global__ void k_wabs(const float* __restrict__ w0, const float* __restrict__ w1,
                       const float* __restrict__ w2) {
    __shared__ float red[256];
    const float* W = (blockIdx.y == 0) ? w0 : ((blockIdx.y == 1) ? w1 : w2);
    float s = 0.f;
    for (int idx = blockIdx.x * 256 + threadIdx.x; idx < NW / 4; idx += 1024 * 256) {
        float4 v = reinterpret_cast<const float4*>(W)[idx];
        s += fabsf(v.x) + fabsf(v.y) + fabsf(v.z) + fabsf(v.w);
    }
    red[threadIdx.x] = s;
    __syncthreads();
    for (int o = 128; o > 0; o >>= 1) {
        if (threadIdx.x < o) red[threadIdx.x] += red[threadIdx.x + o];
        __syncthreads();
    }
    if (threadIdx.x == 0) g_part[blockIdx.y * 1024 + blockIdx.x] = red[0];
}

// ---------------- 2) finalize mean|w| ----------------
__global__ void k_wfin() {
    __shared__ float red[1024];
    int m = blockIdx.x;
    red[threadIdx.x] = g_part[m * 1024 + threadIdx.x];
    __syncthreads();
    for (int o = 512; o > 0; o >>= 1) {
        if (threadIdx.x < o) red[threadIdx.x] += red[threadIdx.x + o];
        __syncthreads();
    }
    if (threadIdx.x == 0) g_wnorm[m] = fmaxf(red[0] / (float)NW, 1e-5f);
}

// ---------------- 3) ternarize weights (mbase selects matrices) ----------------
__global__ void k_wquant(const float* __restrict__ w0, const float* __restrict__ w1,
                         const float* __restrict__ w2, int mbase) {
    int m = mbase + blockIdx.y;
    const float* W = (m == 0) ? w0 : ((m == 1) ? w1 : w2);
    signed char* Q = (m == 0) ? g_wqg : ((m == 1) ? g_wqu : g_wqd);
    float ws = 1.0f / g_wnorm[m];
    int i4 = blockIdx.x * 256 + threadIdx.x;
    const float4* Wv = reinterpret_cast<const float4*>(W);
    int4 o;
    o.x = pack_q4(Wv[i4 * 4 + 0], ws, -1.f, 1.f);
    o.y = pack_q4(Wv[i4 * 4 + 1], ws, -1.f, 1.f);
    o.z = pack_q4(Wv[i4 * 4 + 2], ws, -1.f, 1.f);
    o.w = pack_q4(Wv[i4 * 4 + 3], ws, -1.f, 1.f);
    reinterpret_cast<int4*>(Q)[i4] = o;
}

// ---------------- 4) per-token act_quant of x ----------------
__global__ void k_actq1(const float* __restrict__ x) {
    __shared__ float red[256];
    int t = blockIdx.x;
    const float4* px = reinterpret_cast<const float4*>(x + (size_t)t * H_DIM);
    float4 v0 = px[threadIdx.x * 2], v1 = px[threadIdx.x * 2 + 1];
    float m = fmaxf(fmaxf(fmaxf(fabsf(v0.x), fabsf(v0.y)), fmaxf(fabsf(v0.z), fabsf(v0.w))),
                    fmaxf(fmaxf(fabsf(v1.x), fabsf(v1.y)), fmaxf(fabsf(v1.z), fabsf(v1.w))));
    red[threadIdx.x] = m;
    __syncthreads();
    for (int o = 128; o > 0; o >>= 1) {
        if (threadIdx.x < o) red[threadIdx.x] = fmaxf(red[threadIdx.x], red[threadIdx.x + o]);
        __syncthreads();
    }
    float scale = 128.f / fmaxf(red[0], 1e-5f);
    int p0 = pack_q4(v0, scale, -128.f, 127.f);
    int p1 = pack_q4(v1, scale, -128.f, 127.f);
    reinterpret_cast<int2*>(g_xq + (size_t)t * H_DIM)[threadIdx.x] = make_int2(p0, p1);
    if (threadIdx.x == 0) g_xs[t] = scale;
}

// ---------------- GEMM common geometry ----------------
// BM=128, 128 B-rows, BK=128, 8 warps 2(M)x4(N), warp tile 64x32, 3-stage cp.async,
// ldmatrix fragment loads, 256 threads, 2 CTAs/SM.
#define SSTRIDE 144                 // 128 data + 16 pad: conflict-free stores & ldmatrix
#define STG_SZ  (128 * SSTRIDE)     // 18432 B per operand per stage
#define NSTG    3
#define DSMEM   (2 * NSTG * STG_SZ) // 110592 B

// ---------------- 5) GEMM1: IMMA, gate+up interleaved, SiLU epilogue ----------------
__global__ __launch_bounds__(256, 2) void k_gemm1() {
    extern __shared__ signed char dyn[];
    const int tid = threadIdx.x, wid = tid >> 5, lane = tid & 31;
    const int gid = lane >> 2, tig = lane & 3;
    const int wm = wid >> 2, wn = wid & 3;
    const int m0 = blockIdx.y * 128, n0 = blockIdx.x * 64;
    const signed char* A = g_xq + (size_t)m0 * H_DIM;

    const int rowA = (lane & 7) + ((lane >> 3) & 1) * 8;
    const int bytA = ((lane >> 4) & 1) * 16;
    const int rowB = (lane & 7) + ((lane >> 4) & 1) * 8;
    const int bytB = ((lane >> 3) & 1) * 16;
    const uint32_t dynb = smem_u32(dyn);

    int c[4][4][4];
#pragma unroll
    for (int i = 0; i < 4; i++)
#pragma unroll
        for (int j = 0; j < 4; j++)
#pragma unroll
            for (int q = 0; q < 4; q++) c[i][j][q] = 0;

    auto load_stage = [&](int st, int kb) {
        int koff = kb * 128;
        signed char* dA = dyn + st * STG_SZ;
        signed char* dB = dyn + NSTG * STG_SZ + st * STG_SZ;
#pragma unroll
        for (int l = 0; l < 4; l++) {      // 128 rows x 8 chunks of 16B = 1024 each
            int ch = tid + l * 256;
            int r = ch >> 3, c16 = ch & 7;
            CP_ASYNC16(smem_u32(&dA[r * SSTRIDE + c16 * 16]),
                       A + (size_t)r * H_DIM + koff + c16 * 16);
            int n = n0 + (r >> 1);
            const signed char* W = (r & 1) ? g_wqu : g_wqg;
            CP_ASYNC16(smem_u32(&dB[r * SSTRIDE + c16 * 16]),
                       W + (size_t)n * H_DIM + koff + c16 * 16);
        }
    };

    load_stage(0, 0); CP_COMMIT();
    load_stage(1, 1); CP_COMMIT();

    const int NKB = 16;   // 2048 / 128
    for (int kb = 0; kb < NKB; kb++) {
        if (kb < NKB - 1) { CP_WAIT(1); } else { CP_WAIT(0); }
        __syncthreads();
        if (kb + 2 < NKB) { load_stage((kb + 2) % NSTG, kb + 2); CP_COMMIT(); }
        int st = kb % NSTG;
        uint32_t As = dynb + st * STG_SZ;
        uint32_t Bs = dynb + NSTG * STG_SZ + st * STG_SZ;
#pragma unroll
        for (int ks = 0; ks < 4; ks++) {
            int a[4][4], b[4][2];
#pragma unroll
            for (int mi = 0; mi < 4; mi++) {
                uint32_t ad = As + (uint32_t)(wm * 64 + mi * 16 + rowA) * SSTRIDE + ks * 32 + bytA;
                LDSM_X4(a[mi][0], a[mi][1], a[mi][2], a[mi][3], ad);
            }
#pragma unroll
            for (int np = 0; np < 2; np++) {
                uint32_t bd = Bs + (uint32_t)(wn * 32 + np * 16 + rowB) * SSTRIDE + ks * 32 + bytB;
                LDSM_X4(b[2 * np][0], b[2 * np][1], b[2 * np + 1][0], b[2 * np + 1][1], bd);
            }
#pragma unroll
            for (int mi = 0; mi < 4; mi++)
#pragma unroll
                for (int ni = 0; ni < 4; ni++) MMA_S8(c[mi][ni], a[mi], b[ni]);
        }
        __syncthreads();
    }

    float fg = g_wnorm[0], fu = g_wnorm[1];
#pragma unroll
    for (int mi = 0; mi < 4; mi++) {
        int t1 = m0 + wm * 64 + mi * 16 + gid, t2 = t1 + 8;
        float i1 = 1.0f / g_xs[t1], i2 = 1.0f / g_xs[t2];
#pragma unroll
        for (int ni = 0; ni < 4; ni++) {
            int n = n0 + wn * 16 + ni * 4 + tig;
            float gv1 = (float)c[mi][ni][0] * fg * i1;
            float uv1 = (float)c[mi][ni][1] * fu * i1;
            g_inter[(size_t)t1 * I_DIM + n] = gv1 / (1.0f + __expf(-gv1)) * uv1;
            float gv2 = (float)c[mi][ni][2] * fg * i2;
            float uv2 = (float)c[mi][ni][3] * fu * i2;
            g_inter[(size_t)t2 * I_DIM + n] = gv2 / (1.0f + __expf(-gv2)) * uv2;
        }
    }
}

// ---------------- 6) FWHT-8192 + act_quant #2 (register-chunked) ----------------
__global__ __launch_bounds__(512) void k_fwht() {
    __shared__ float s[8192];
    __shared__ float red[512];
    const int tid = threadIdx.x;
    const int t = blockIdx.x;
    float v[16];
    float4* vv = reinterpret_cast<float4*>(v);

    const float4* src = reinterpret_cast<const float4*>(g_inter + (size_t)t * I_DIM);
#pragma unroll
    for (int i = 0; i < 4; i++) vv[i] = src[tid * 4 + i];
#pragma unroll
    for (int h = 1; h < 16; h <<= 1)
#pragma unroll
        for (int i = 0; i < 16; i++)
            if ((i & h) == 0) {
                float a = v[i], b = v[i + h];
                v[i] = a + b; v[i + h] = a - b;
            }
#pragma unroll
    for (int i = 0; i < 4; i++) reinterpret_cast<float4*>(s)[tid * 4 + i] = vv[i];
    __syncthreads();

    int b2 = (tid & 15) + ((tid >> 4) << 8);
#pragma unroll
    for (int j = 0; j < 16; j++) v[j] = s[b2 + 16 * j];
#pragma unroll
    for (int h = 1; h < 16; h <<= 1)
#pragma unroll
        for (int j = 0; j < 16; j++)
            if ((j & h) == 0) {
                float a = v[j], b = v[j + h];
                v[j] = a + b; v[j + h] = a - b;
            }
#pragma unroll
    for (int j = 0; j < 16; j++) s[b2 + 16 * j] = v[j];
    __syncthreads();

    int b3 = (tid & 255) + ((tid >> 8) << 12);
#pragma unroll
    for (int j = 0; j < 16; j++) v[j] = s[b3 + 256 * j];
#pragma unroll
    for (int h = 1; h < 16; h <<= 1)
#pragma unroll
        for (int j = 0; j < 16; j++)
            if ((j & h) == 0) {
                float a = v[j], b = v[j + h];
                v[j] = a + b; v[j + h] = a - b;
            }
#pragma unroll
    for (int j = 0; j < 16; j++) s[b3 + 256 * j] = v[j];
    __syncthreads();

    const float rn = 1.1048543456039805e-02f;  // 1/sqrt(8192)
    float lo[8], hi[8];
    float m = 0.f;
#pragma unroll
    for (int q = 0; q < 8; q++) {
        float a = s[tid * 8 + q], b = s[tid * 8 + q + 4096];
        float na = (a + b) * rn, nb = (a - b) * rn;
        lo[q] = na; hi[q] = nb;
        m = fmaxf(m, fmaxf(fabsf(na), fabsf(nb)));
    }
    red[tid] = m;
    __syncthreads();
    for (int o = 256; o > 0; o >>= 1) {
        if (tid < o) red[tid] = fmaxf(red[tid], red[tid + o]);
        __syncthreads();
    }
    float scale = 128.f / fmaxf(red[0], 1e-5f);
    float4* lv = reinterpret_cast<float4*>(lo);
    float4* hv = reinterpret_cast<float4*>(hi);
    int2 plo = make_int2(pack_q4(lv[0], scale, -128.f, 127.f),
                         pack_q4(lv[1], scale, -128.f, 127.f));
    int2 phi = make_int2(pack_q4(hv[0], scale, -128.f, 127.f),
                         pack_q4(hv[1], scale, -128.f, 127.f));
    int2* orow = reinterpret_cast<int2*>(g_aq2 + (size_t)t * I_DIM);
    orow[tid] = plo;
    orow[tid + 512] = phi;
    if (tid == 0) g_as2[t] = scale;
}

// ---------------- 7) GEMM2: IMMA down projection ----------------
__global__ __launch_bounds__(256, 2) void k_gemm2(float* __restrict__ out) {
    extern __shared__ signed char dyn[];
    const int tid = threadIdx.x, wid = tid >> 5, lane = tid & 31;
    const int gid = lane >> 2, tig = lane & 3;
    const int wm = wid >> 2, wn = wid & 3;
    const int m0 = blockIdx.y * 128, n0 = blockIdx.x * 128;
    const signed char* A = g_aq2 + (size_t)m0 * I_DIM;
    const signed char* B = g_wqd + (size_t)n0 * I_DIM;

    const int rowA = (lane & 7) + ((lane >> 3) & 1) * 8;
    const int bytA = ((lane >> 4) & 1) * 16;
    const int rowB = (lane & 7) + ((lane >> 4) & 1) * 8;
    const int bytB = ((lane >> 3) & 1) * 16;
    const uint32_t dynb = smem_u32(dyn);

    int c[4][4][4];
#pragma unroll
    for (int i = 0; i < 4; i++)
#pragma unroll
        for (int j = 0; j < 4; j++)
#pragma unroll
            for (int q = 0; q < 4; q++) c[i][j][q] = 0;

    auto load_stage = [&](int st, int kb) {
        int koff = kb * 128;
        signed char* dA = dyn + st * STG_SZ;
        signed char* dB = dyn + NSTG * STG_SZ + st * STG_SZ;
#pragma unroll
        for (int l = 0; l < 4; l++) {
            int ch = tid + l * 256;
            int r = ch >> 3, c16 = ch & 7;
            CP_ASYNC16(smem_u32(&dA[r * SSTRIDE + c16 * 16]),
                       A + (size_t)r * I_DIM + koff + c16 * 16);
            CP_ASYNC16(smem_u32(&dB[r * SSTRIDE + c16 * 16]),
                       B + (size_t)r * I_DIM + koff + c16 * 16);
        }
    };

    load_stage(0, 0); CP_COMMIT();
    load_stage(1, 1); CP_COMMIT();

    const int NKB = 64;   // 8192 / 128
    for (int kb = 0; kb < NKB; kb++) {
        if (kb < NKB - 1) { CP_WAIT(1); } else { CP_WAIT(0); }
        __syncthreads();
        if (kb + 2 < NKB) { load_stage((kb + 2) % NSTG, kb + 2); CP_COMMIT(); }
        int st = kb % NSTG;
        uint32_t As = dynb + st * STG_SZ;
        uint32_t Bs = dynb + NSTG * STG_SZ + st * STG_SZ;
#pragma unroll
        for (int ks = 0; ks < 4; ks++) {
            int a[4][4], b[4][2];
#pragma unroll
            for (int mi = 0; mi < 4; mi++) {
                uint32_t ad = As + (uint32_t)(wm * 64 + mi * 16 + rowA) * SSTRIDE + ks * 32 + bytA;
                LDSM_X4(a[mi][0], a[mi][1], a[mi][2], a[mi][3], ad);
            }
#pragma unroll
            for (int np = 0; np < 2; np++) {
                uint32_t bd = Bs + (uint32_t)(wn * 32 + np * 16 + rowB) * SSTRIDE + ks * 32 + bytB;
                LDSM_X4(b[2 * np][0], b[2 * np][1], b[2 * np + 1][0], b[2 * np + 1][1], bd);
            }
#pragma unroll
            for (int mi = 0; mi < 4; mi++)
#pragma unroll
                for (int ni = 0; ni < 4; ni++) MMA_S8(c[mi][ni], a[mi], b[ni]);
        }
        __syncthreads();
    }

    float fw = g_wnorm[2];
#pragma unroll
    for (int mi = 0; mi < 4; mi++) {
        int t1 = m0 + wm * 64 + mi * 16 + gid, t2 = t1 + 8;
        float f1 = fw / g_as2[t1], f2 = fw / g_as2[t2];
#pragma unroll
        for (int ni = 0; ni < 4; ni++) {
            int col = n0 + wn * 32 + ni * 8 + tig * 2;
            float2 o1 = make_float2((float)c[mi][ni][0] * f1, (float)c[mi][ni][1] * f1);
            float2 o2 = make_float2((float)c[mi][ni][2] * f2, (float)c[mi][ni][3] * f2);
            *reinterpret_cast<float2*>(&out[(size_t)t1 * H_DIM + col]) = o1;
            *reinterpret_cast<float2*>(&out[(size_t)t2 * H_DIM + col]) = o2;
        }
    }
}

// ---------------- launch (multi-stream fork/join for graph concurrency) ----------------
extern "C" void kernel_launch(void* const* d_in, const int* in_sizes, int n_in,
                              void* d_out, int out_size) {
    const float* x  = (const float*)d_in[0];
    const float* wg = (const float*)d_in[1];
    const float* wu = (const float*)d_in[2];
    const float* wd = (const float*)d_in[3];
    float* out = (float*)d_out;

    static cudaStream_t s2 = nullptr, s3 = nullptr;
    static cudaEvent_t evRoot = nullptr, evFin = nullptr, evActq = nullptr, evWd = nullptr;
    static int configured = 0;
    if (!configured) {
        cudaFuncSetAttribute(k_gemm1, cudaFuncAttributeMaxDynamicSharedMemorySize, DSMEM);
        cudaFuncSetAttribute(k_gemm2, cudaFuncAttributeMaxDynamicSharedMemorySize, DSMEM);
        cudaStreamCreateWithFlags(&s2, cudaStreamNonBlocking);
        cudaStreamCreateWithFlags(&s3, cudaStreamNonBlocking);
        cudaEventCreateWithFlags(&evRoot, cudaEventDisableTiming);
        cudaEventCreateWithFlags(&evFin,  cudaEventDisableTiming);
        cudaEventCreateWithFlags(&evActq, cudaEventDisableTiming);
        cudaEventCreateWithFlags(&evWd,   cudaEventDisableTiming);
        configured = 1;
    }

    // fork: actq1 (x only) runs concurrent with the weight chain
    cudaEventRecord(evRoot, 0);
    cudaStreamWaitEvent(s2, evRoot, 0);
    k_actq1<<<T_TOK, 256, 0, s2>>>(x);
    cudaEventRecord(evActq, s2);

    // main chain: |w| mean for all three matrices
    k_wabs<<<dim3(1024, 3), 256>>>(wg, wu, wd);
    k_wfin<<<3, 1024>>>();
    cudaEventRecord(evFin, 0);

    // side branch: w_down ternarization, joins before gemm2
    cudaStreamWaitEvent(s3, evFin, 0);
    k_wquant<<<dim3(4096, 1), 256, 0, s3>>>(wg, wu, wd, 2);
    cudaEventRecord(evWd, s3);

    // main: gate+up ternarization, then GEMM1 (joins actq1)
    k_wquant<<<dim3(4096, 2), 256>>>(wg, wu, wd, 0);
    cudaStreamWaitEvent(0, evActq, 0);
    k_gemm1<<<dim3(I_DIM / 64, T_TOK / 128), 256, DSMEM>>>();
    k_fwht<<<T_TOK, 512>>>();
    cudaStreamWaitEvent(0, evWd, 0);
    k_gemm2<<<dim3(H_DIM / 128, T_TOK / 128), 256, DSMEM>>>(out);
}